// round 1
// baseline (speedup 1.0000x reference)
#include <cuda_runtime.h>
#include <math.h>

// ---------------------------------------------------------------------------
// Problem constants
// ---------------------------------------------------------------------------
#define BATCH  4
#define NTOK   1024
#define DMODEL 1024
#define HEADS  16
#define HDIM   64
#define ROWS   (BATCH * NTOK)     // 4096
#define MLPD   4096
#define SIXD   (6 * DMODEL)       // 6144
#define EPS    1e-6f
#define ATTN_SCALE 0.125f         // 64^-0.5

// ---------------------------------------------------------------------------
// Scratch (device globals: no allocations allowed)
// ---------------------------------------------------------------------------
__device__ float g_mod[BATCH * SIXD];          // adaLN modulation [B, 6D]
__device__ float g_h  [ROWS * DMODEL];         // LN+modulate output (reused)
__device__ float g_q  [ROWS * DMODEL];         // Q  [B,N,H,DH]
__device__ float g_kv [ROWS * 2 * DMODEL];     // KV [B,N, 2D] (k cols 0..1023, v 1024..2047)
__device__ float g_att[ROWS * DMODEL];         // attention output [B,N,H,DH]
__device__ float g_m1 [ROWS * MLPD];           // MLP hidden

// ---------------------------------------------------------------------------
// Helpers
// ---------------------------------------------------------------------------
__device__ __forceinline__ float gelu_tanh(float y) {
    float y3 = y * y * y;
    return 0.5f * y * (1.0f + tanhf(0.7978845608028654f * (y + 0.044715f * y3)));
}

// ---------------------------------------------------------------------------
// Kernel 1: mod = silu(c) @ Wada + bada        [4, 6144]
// grid (6144/256, 4), block 256
// ---------------------------------------------------------------------------
__global__ void __launch_bounds__(256) ada_mod_kernel(
    const float* __restrict__ c, const float* __restrict__ Wada,
    const float* __restrict__ bada, float* __restrict__ mod)
{
    __shared__ float sc[DMODEL];
    int b = blockIdx.y;
    int n = blockIdx.x * 256 + threadIdx.x;
    for (int i = threadIdx.x; i < DMODEL; i += 256) {
        float v = c[b * DMODEL + i];
        sc[i] = v / (1.0f + __expf(-v));
    }
    __syncthreads();
    float acc = 0.0f;
    const float* wp = Wada + n;
    for (int k = 0; k < DMODEL; k++)
        acc = fmaf(sc[k], wp[(size_t)k * SIXD], acc);
    mod[b * SIXD + n] = acc + bada[n];
}

// ---------------------------------------------------------------------------
// Kernel 2: out = LN(x) * (1 + scale) + shift, per row (D=1024)
// grid 4096, block 256 (4 floats per thread via float4)
// ---------------------------------------------------------------------------
__global__ void __launch_bounds__(256) ln_mod_kernel(
    const float* __restrict__ x, const float* __restrict__ mod,
    int shiftOff, int scaleOff, float* __restrict__ out)
{
    __shared__ float red[8];
    int row = blockIdx.x;
    int b = row >> 10;
    const float4* xr = (const float4*)(x + (size_t)row * DMODEL);
    float4 v = xr[threadIdx.x];

    // mean
    float s = v.x + v.y + v.z + v.w;
    #pragma unroll
    for (int o = 16; o; o >>= 1) s += __shfl_xor_sync(0xffffffffu, s, o);
    if ((threadIdx.x & 31) == 0) red[threadIdx.x >> 5] = s;
    __syncthreads();
    float tot = 0.f;
    #pragma unroll
    for (int w = 0; w < 8; w++) tot += red[w];
    float mean = tot * (1.0f / DMODEL);
    __syncthreads();

    // variance
    float dx = v.x - mean, dy = v.y - mean, dz = v.z - mean, dw = v.w - mean;
    float q = dx * dx + dy * dy + dz * dz + dw * dw;
    #pragma unroll
    for (int o = 16; o; o >>= 1) q += __shfl_xor_sync(0xffffffffu, q, o);
    if ((threadIdx.x & 31) == 0) red[threadIdx.x >> 5] = q;
    __syncthreads();
    float vtot = 0.f;
    #pragma unroll
    for (int w = 0; w < 8; w++) vtot += red[w];
    float rstd = rsqrtf(vtot * (1.0f / DMODEL) + EPS);

    int c0 = threadIdx.x * 4;
    const float* base = mod + (size_t)b * SIXD;
    float4 shv = *(const float4*)(base + shiftOff + c0);
    float4 scv = *(const float4*)(base + scaleOff + c0);
    float4 r;
    r.x = dx * rstd * (1.0f + scv.x) + shv.x;
    r.y = dy * rstd * (1.0f + scv.y) + shv.y;
    r.z = dz * rstd * (1.0f + scv.z) + shv.z;
    r.w = dw * rstd * (1.0f + scv.w) + shv.w;
    ((float4*)(out + (size_t)row * DMODEL))[threadIdx.x] = r;
}

// ---------------------------------------------------------------------------
// Kernel 3: SGEMM  C[M,N] = A[M,K] @ B[K,N] (+ epilogue)
//   EPI 0: C = acc + bias[n]
//   EPI 1: C = gelu(acc + bias[n])
//   EPI 2: C = res[m,n] + gate[(m>>10)*6144 + n] * (acc + bias[n])
// 128x128x16 tile, 8x8 per thread, 256 threads. M,N,K multiples of tile dims.
// ---------------------------------------------------------------------------
template <int EPI>
__global__ void __launch_bounds__(256) sgemm_kernel(
    const float* __restrict__ A, const float* __restrict__ B,
    const float* __restrict__ bias, const float* __restrict__ res,
    const float* __restrict__ gate, float* __restrict__ C,
    int M, int N, int K)
{
    constexpr int BM = 128, BN = 128, BK = 16;
    __shared__ float As[BK][BM];
    __shared__ float Bs[BK][BN];

    const int tid = threadIdx.x;
    const int tx = tid & 15;          // 0..15 -> col group
    const int ty = tid >> 4;          // 0..15 -> row group
    const int bm = blockIdx.y * BM;
    const int bn = blockIdx.x * BN;

    float acc[8][8];
    #pragma unroll
    for (int i = 0; i < 8; i++)
        #pragma unroll
        for (int j = 0; j < 8; j++) acc[i][j] = 0.f;

    const int aRow = tid >> 2;        // 0..63
    const int aK4  = tid & 3;         // float4 slot along K
    const int bK   = tid >> 5;        // 0..7
    const int bN4  = tid & 31;        // float4 slot along N

    const float* Aptr = A + (size_t)bm * K;
    const float* Bptr = B + bn;

    for (int k0 = 0; k0 < K; k0 += BK) {
        #pragma unroll
        for (int i = 0; i < 2; i++) {
            int r = aRow + i * 64;
            float4 v = *(const float4*)(Aptr + (size_t)r * K + k0 + aK4 * 4);
            As[aK4 * 4 + 0][r] = v.x;
            As[aK4 * 4 + 1][r] = v.y;
            As[aK4 * 4 + 2][r] = v.z;
            As[aK4 * 4 + 3][r] = v.w;
        }
        #pragma unroll
        for (int i = 0; i < 2; i++) {
            int kk = bK + i * 8;
            float4 v = *(const float4*)(Bptr + (size_t)(k0 + kk) * N + bN4 * 4);
            *(float4*)(&Bs[kk][bN4 * 4]) = v;
        }
        __syncthreads();

        #pragma unroll
        for (int kk = 0; kk < BK; kk++) {
            float a[8], bb[8];
            #pragma unroll
            for (int i = 0; i < 8; i++) a[i] = As[kk][ty * 8 + i];
            #pragma unroll
            for (int j = 0; j < 8; j++) bb[j] = Bs[kk][tx * 8 + j];
            #pragma unroll
            for (int i = 0; i < 8; i++)
                #pragma unroll
                for (int j = 0; j < 8; j++)
                    acc[i][j] = fmaf(a[i], bb[j], acc[i][j]);
        }
        __syncthreads();
    }

    #pragma unroll
    for (int i = 0; i < 8; i++) {
        int row = bm + ty * 8 + i;
        size_t rbase = (size_t)row * N;
        size_t gbase = (size_t)(row >> 10) * SIXD;
        #pragma unroll
        for (int j = 0; j < 8; j++) {
            int col = bn + tx * 8 + j;
            float y = acc[i][j] + bias[col];
            if (EPI == 1) y = gelu_tanh(y);
            if (EPI == 2) y = res[rbase + col] + gate[gbase + col] * y;
            C[rbase + col] = y;
        }
    }
}

// ---------------------------------------------------------------------------
// Kernel 4: flash attention, fp32, head dim 64, N=1024
// grid (N/64, B*H), block 256 (16x16 threads, 4x4 register tiles)
// dynamic smem: Qs/Ks/Vs/Ss [64][65] + rowM/rowL/rowC [64]
// ---------------------------------------------------------------------------
#define ATTN_SMEM_FLOATS (4 * 64 * 65 + 3 * 64)

__global__ void __launch_bounds__(256) attn_kernel(
    const float* __restrict__ q, const float* __restrict__ kv,
    float* __restrict__ out)
{
    extern __shared__ float sm[];
    float (*Qs)[65] = reinterpret_cast<float(*)[65]>(sm);
    float (*Ks)[65] = reinterpret_cast<float(*)[65]>(sm + 64 * 65);
    float (*Vs)[65] = reinterpret_cast<float(*)[65]>(sm + 2 * 64 * 65);
    float (*Ss)[65] = reinterpret_cast<float(*)[65]>(sm + 3 * 64 * 65);
    float* rowM = sm + 4 * 64 * 65;
    float* rowL = rowM + 64;
    float* rowC = rowL + 64;

    const int tid = threadIdx.x;
    const int tx = tid & 15, ty = tid >> 4;
    const int bh = blockIdx.y;
    const int b = bh >> 4, h = bh & 15;
    const int q0 = blockIdx.x * 64;

    // load Q tile: q[b, q0+r, h, :]  (64 rows x 64)
    for (int t = tid; t < 64 * 16; t += 256) {
        int r = t >> 4, d4 = t & 15;
        float4 v = *(const float4*)(q +
            ((((size_t)(b * NTOK + q0 + r)) * HEADS + h) << 6) + d4 * 4);
        Qs[r][d4 * 4 + 0] = v.x; Qs[r][d4 * 4 + 1] = v.y;
        Qs[r][d4 * 4 + 2] = v.z; Qs[r][d4 * 4 + 3] = v.w;
    }
    if (tid < 64) { rowM[tid] = -INFINITY; rowL[tid] = 0.f; }

    float o[4][4];
    #pragma unroll
    for (int i = 0; i < 4; i++)
        #pragma unroll
        for (int j = 0; j < 4; j++) o[i][j] = 0.f;

    for (int jt = 0; jt < NTOK / 64; jt++) {
        int j0 = jt * 64;
        // load K, V tiles
        for (int t = tid; t < 64 * 16; t += 256) {
            int r = t >> 4, d4 = t & 15;
            size_t base = (size_t)(b * NTOK + j0 + r) * (2 * DMODEL) + h * HDIM + d4 * 4;
            float4 kvec = *(const float4*)(kv + base);
            float4 vvec = *(const float4*)(kv + base + DMODEL);
            Ks[r][d4 * 4 + 0] = kvec.x; Ks[r][d4 * 4 + 1] = kvec.y;
            Ks[r][d4 * 4 + 2] = kvec.z; Ks[r][d4 * 4 + 3] = kvec.w;
            Vs[r][d4 * 4 + 0] = vvec.x; Vs[r][d4 * 4 + 1] = vvec.y;
            Vs[r][d4 * 4 + 2] = vvec.z; Vs[r][d4 * 4 + 3] = vvec.w;
        }
        __syncthreads();

        // S = scale * Q @ K^T  (64x64), 4x4 per thread
        float s4[4][4];
        #pragma unroll
        for (int i = 0; i < 4; i++)
            #pragma unroll
            for (int j = 0; j < 4; j++) s4[i][j] = 0.f;
        #pragma unroll 8
        for (int kk = 0; kk < 64; kk++) {
            float a[4], bb[4];
            #pragma unroll
            for (int i = 0; i < 4; i++) a[i] = Qs[ty * 4 + i][kk];
            #pragma unroll
            for (int j = 0; j < 4; j++) bb[j] = Ks[tx * 4 + j][kk];
            #pragma unroll
            for (int i = 0; i < 4; i++)
                #pragma unroll
                for (int j = 0; j < 4; j++)
                    s4[i][j] = fmaf(a[i], bb[j], s4[i][j]);
        }
        #pragma unroll
        for (int i = 0; i < 4; i++)
            #pragma unroll
            for (int j = 0; j < 4; j++)
                Ss[ty * 4 + i][tx * 4 + j] = s4[i][j] * ATTN_SCALE;
        __syncthreads();

        // online softmax: warp w owns rows w*8 .. w*8+7
        {
            int w = tid >> 5, lane = tid & 31;
            for (int rr = 0; rr < 8; rr++) {
                int r = w * 8 + rr;
                float v0 = Ss[r][lane], v1 = Ss[r][lane + 32];
                float mx = fmaxf(v0, v1);
                #pragma unroll
                for (int off = 16; off; off >>= 1)
                    mx = fmaxf(mx, __shfl_xor_sync(0xffffffffu, mx, off));
                float mOld = rowM[r];
                float mNew = fmaxf(mOld, mx);
                float p0 = __expf(v0 - mNew), p1 = __expf(v1 - mNew);
                float ssum = p0 + p1;
                #pragma unroll
                for (int off = 16; off; off >>= 1)
                    ssum += __shfl_xor_sync(0xffffffffu, ssum, off);
                Ss[r][lane] = p0; Ss[r][lane + 32] = p1;
                if (lane == 0) {
                    float corr = __expf(mOld - mNew);
                    rowC[r] = corr;
                    rowL[r] = rowL[r] * corr + ssum;
                    rowM[r] = mNew;
                }
            }
        }
        __syncthreads();

        // O = O * corr + P @ V
        float cf[4];
        #pragma unroll
        for (int i = 0; i < 4; i++) cf[i] = rowC[ty * 4 + i];
        #pragma unroll
        for (int i = 0; i < 4; i++)
            #pragma unroll
            for (int j = 0; j < 4; j++) o[i][j] *= cf[i];
        #pragma unroll 8
        for (int kk = 0; kk < 64; kk++) {
            float p[4], vv[4];
            #pragma unroll
            for (int i = 0; i < 4; i++) p[i] = Ss[ty * 4 + i][kk];
            #pragma unroll
            for (int j = 0; j < 4; j++) vv[j] = Vs[kk][tx * 4 + j];
            #pragma unroll
            for (int i = 0; i < 4; i++)
                #pragma unroll
                for (int j = 0; j < 4; j++)
                    o[i][j] = fmaf(p[i], vv[j], o[i][j]);
        }
        __syncthreads();
    }

    // normalize and write out[b, q0+qi, h, d]
    #pragma unroll
    for (int i = 0; i < 4; i++) {
        int qi = ty * 4 + i;
        float inv = 1.0f / rowL[qi];
        size_t base = (((size_t)(b * NTOK + q0 + qi)) * HEADS + h) << 6;
        #pragma unroll
        for (int j = 0; j < 4; j++)
            out[base + tx * 4 + j] = o[i][j] * inv;
    }
}

// ---------------------------------------------------------------------------
// Launch
// ---------------------------------------------------------------------------
extern "C" void kernel_launch(void* const* d_in, const int* in_sizes, int n_in,
                              void* d_out, int out_size)
{
    const float* x    = (const float*)d_in[0];
    const float* c    = (const float*)d_in[1];
    const float* Wq   = (const float*)d_in[2];
    const float* bq   = (const float*)d_in[3];
    const float* Wkv  = (const float*)d_in[4];
    const float* bkv  = (const float*)d_in[5];
    const float* Wo   = (const float*)d_in[6];
    const float* bo   = (const float*)d_in[7];
    const float* W1   = (const float*)d_in[8];
    const float* b1   = (const float*)d_in[9];
    const float* W2   = (const float*)d_in[10];
    const float* b2   = (const float*)d_in[11];
    const float* Wada = (const float*)d_in[12];
    const float* bada = (const float*)d_in[13];
    float* out = (float*)d_out;

    float *mod, *h, *q, *kv, *att, *m1;
    cudaGetSymbolAddress((void**)&mod, g_mod);
    cudaGetSymbolAddress((void**)&h,   g_h);
    cudaGetSymbolAddress((void**)&q,   g_q);
    cudaGetSymbolAddress((void**)&kv,  g_kv);
    cudaGetSymbolAddress((void**)&att, g_att);
    cudaGetSymbolAddress((void**)&m1,  g_m1);

    const int attnSmem = ATTN_SMEM_FLOATS * (int)sizeof(float);
    cudaFuncSetAttribute(attn_kernel,
                         cudaFuncAttributeMaxDynamicSharedMemorySize, attnSmem);

    // 1) adaLN modulation
    ada_mod_kernel<<<dim3(SIXD / 256, BATCH), 256>>>(c, Wada, bada, mod);

    // 2) h = modulate(LN(x), sh_msa, sc_msa)
    ln_mod_kernel<<<ROWS, 256>>>(x, mod, 0 * DMODEL, 1 * DMODEL, h);

    // 3) q = h @ Wq + bq ; kv = h @ Wkv + bkv
    sgemm_kernel<0><<<dim3(DMODEL / 128, ROWS / 128), 256>>>(
        h, Wq, bq, nullptr, nullptr, q, ROWS, DMODEL, DMODEL);
    sgemm_kernel<0><<<dim3(2 * DMODEL / 128, ROWS / 128), 256>>>(
        h, Wkv, bkv, nullptr, nullptr, kv, ROWS, 2 * DMODEL, DMODEL);

    // 4) attention
    attn_kernel<<<dim3(NTOK / 64, BATCH * HEADS), 256, attnSmem>>>(q, kv, att);

    // 5) x1 = x + g_msa * (att @ Wo + bo)   -> d_out
    sgemm_kernel<2><<<dim3(DMODEL / 128, ROWS / 128), 256>>>(
        att, Wo, bo, x, mod + 2 * DMODEL, out, ROWS, DMODEL, DMODEL);

    // 6) h2 = modulate(LN(x1), sh_mlp, sc_mlp)
    ln_mod_kernel<<<ROWS, 256>>>(out, mod, 3 * DMODEL, 4 * DMODEL, h);

    // 7) m1 = gelu(h2 @ W1 + b1)
    sgemm_kernel<1><<<dim3(MLPD / 128, ROWS / 128), 256>>>(
        h, W1, b1, nullptr, nullptr, m1, ROWS, MLPD, DMODEL);

    // 8) x2 = x1 + g_mlp * (m1 @ W2 + b2)   -> d_out (read-modify-write own elem)
    sgemm_kernel<2><<<dim3(DMODEL / 128, ROWS / 128), 256>>>(
        m1, W2, b2, out, mod + 5 * DMODEL, out, ROWS, DMODEL, MLPD);
}

// round 4
// speedup vs baseline: 1.4516x; 1.4516x over previous
#include <cuda_runtime.h>
#include <math.h>
#include <stdint.h>

// ---------------------------------------------------------------------------
// Problem constants
// ---------------------------------------------------------------------------
#define BATCH  4
#define NTOK   1024
#define DMODEL 1024
#define HEADS  16
#define HDIM   64
#define ROWS   (BATCH * NTOK)     // 4096
#define MLPD   4096
#define SIXD   (6 * DMODEL)       // 6144
#define EPS    1e-6f
#define ATTN_SCALE 0.125f         // 64^-0.5

// ---------------------------------------------------------------------------
// Scratch (device globals: no allocations allowed)
// ---------------------------------------------------------------------------
__device__ float g_mod[BATCH * SIXD];
__device__ float g_h  [ROWS * DMODEL];
__device__ float g_q  [ROWS * DMODEL];
__device__ float g_kv [ROWS * 2 * DMODEL];
__device__ float g_att[ROWS * DMODEL];
__device__ float g_m1 [ROWS * MLPD];

// ---------------------------------------------------------------------------
// Helpers
// ---------------------------------------------------------------------------
__device__ __forceinline__ float gelu_tanh(float y) {
    float y3 = y * y * y;
    return 0.5f * y * (1.0f + tanhf(0.7978845608028654f * (y + 0.044715f * y3)));
}

// tf32 destination is an opaque b32: output operand MUST be "=r" (not "=f").
__device__ __forceinline__ float to_tf32(float x) {
    uint32_t y;
    asm("cvt.rna.tf32.f32 %0, %1;" : "=r"(y) : "f"(x));
    return __uint_as_float(y);
}

__device__ __forceinline__ void mma_tf32(
    float& d0, float& d1, float& d2, float& d3,
    uint32_t a0, uint32_t a1, uint32_t a2, uint32_t a3,
    uint32_t b0, uint32_t b1)
{
    asm volatile(
        "mma.sync.aligned.m16n8k8.row.col.f32.tf32.tf32.f32 "
        "{%0,%1,%2,%3}, {%4,%5,%6,%7}, {%8,%9}, {%0,%1,%2,%3};"
        : "+f"(d0), "+f"(d1), "+f"(d2), "+f"(d3)
        : "r"(a0), "r"(a1), "r"(a2), "r"(a3), "r"(b0), "r"(b1));
}

// ---------------------------------------------------------------------------
// Kernel 1: mod = silu(c) @ Wada + bada        [4, 6144]
// ---------------------------------------------------------------------------
__global__ void __launch_bounds__(256) ada_mod_kernel(
    const float* __restrict__ c, const float* __restrict__ Wada,
    const float* __restrict__ bada, float* __restrict__ mod)
{
    __shared__ float sc[DMODEL];
    int b = blockIdx.y;
    int n = blockIdx.x * 256 + threadIdx.x;
    for (int i = threadIdx.x; i < DMODEL; i += 256) {
        float v = c[b * DMODEL + i];
        sc[i] = v / (1.0f + __expf(-v));
    }
    __syncthreads();
    float acc = 0.0f;
    const float* wp = Wada + n;
    for (int k = 0; k < DMODEL; k++)
        acc = fmaf(sc[k], wp[(size_t)k * SIXD], acc);
    mod[b * SIXD + n] = acc + bada[n];
}

// ---------------------------------------------------------------------------
// Kernel 2: out = LN(x) * (1 + scale) + shift, per row (D=1024)
// ---------------------------------------------------------------------------
__global__ void __launch_bounds__(256) ln_mod_kernel(
    const float* __restrict__ x, const float* __restrict__ mod,
    int shiftOff, int scaleOff, float* __restrict__ out)
{
    __shared__ float red[8];
    int row = blockIdx.x;
    int b = row >> 10;
    const float4* xr = (const float4*)(x + (size_t)row * DMODEL);
    float4 v = xr[threadIdx.x];

    float s = v.x + v.y + v.z + v.w;
    #pragma unroll
    for (int o = 16; o; o >>= 1) s += __shfl_xor_sync(0xffffffffu, s, o);
    if ((threadIdx.x & 31) == 0) red[threadIdx.x >> 5] = s;
    __syncthreads();
    float tot = 0.f;
    #pragma unroll
    for (int w = 0; w < 8; w++) tot += red[w];
    float mean = tot * (1.0f / DMODEL);
    __syncthreads();

    float dx = v.x - mean, dy = v.y - mean, dz = v.z - mean, dw = v.w - mean;
    float q = dx * dx + dy * dy + dz * dz + dw * dw;
    #pragma unroll
    for (int o = 16; o; o >>= 1) q += __shfl_xor_sync(0xffffffffu, q, o);
    if ((threadIdx.x & 31) == 0) red[threadIdx.x >> 5] = q;
    __syncthreads();
    float vtot = 0.f;
    #pragma unroll
    for (int w = 0; w < 8; w++) vtot += red[w];
    float rstd = rsqrtf(vtot * (1.0f / DMODEL) + EPS);

    int c0 = threadIdx.x * 4;
    const float* base = mod + (size_t)b * SIXD;
    float4 shv = *(const float4*)(base + shiftOff + c0);
    float4 scv = *(const float4*)(base + scaleOff + c0);
    float4 r;
    r.x = dx * rstd * (1.0f + scv.x) + shv.x;
    r.y = dy * rstd * (1.0f + scv.y) + shv.y;
    r.z = dz * rstd * (1.0f + scv.z) + shv.z;
    r.w = dw * rstd * (1.0f + scv.w) + shv.w;
    ((float4*)(out + (size_t)row * DMODEL))[threadIdx.x] = r;
}

// ---------------------------------------------------------------------------
// Kernel 3: TF32 tensor-core GEMM  C[M,N] = A[M,K] @ B[K,N] (+ epilogue)
//   EPI 0: C = acc + bias[n]
//   EPI 1: C = gelu(acc + bias[n])
//   EPI 2: C = res[m,n] + gate[(m>>10)*6144 + n] * (acc + bias[n])
// Block tile 128x128x32, 8 warps (2m x 4n), warp tile 64x32,
// mma.sync.m16n8k8 tf32. M,N multiples of 128; K multiple of 32.
// ---------------------------------------------------------------------------
template <int EPI>
__global__ void __launch_bounds__(256, 2) mma_gemm_kernel(
    const float* __restrict__ A, const float* __restrict__ B,
    const float* __restrict__ bias, const float* __restrict__ res,
    const float* __restrict__ gate, float* __restrict__ C,
    int M, int N, int K)
{
    __shared__ float As[128][36];   // [row][k]  (pad 36: conflict-free frags)
    __shared__ float Bs[128][36];   // [col][k]  (B transposed on load)

    const int tid  = threadIdx.x;
    const int lane = tid & 31;
    const int warp = tid >> 5;
    const int wm   = warp & 1;      // 0..1 -> 64-row band
    const int wn   = warp >> 1;     // 0..3 -> 32-col band
    const int bm   = blockIdx.y * 128;
    const int bn   = blockIdx.x * 128;

    const int g  = lane >> 2;       // group id 0..7
    const int tg = lane & 3;        // thread-in-group 0..3

    float acc[4][4][4];
    #pragma unroll
    for (int i = 0; i < 4; i++)
        #pragma unroll
        for (int j = 0; j < 4; j++)
            #pragma unroll
            for (int r = 0; r < 4; r++) acc[i][j][r] = 0.f;

    // global load indices
    const int aRowStep = tid >> 3;      // 0..31
    const int aK4      = (tid & 7) * 4; // 0,4,..28
    const int bKStep   = tid >> 5;      // 0..7
    const int bN4      = (tid & 31) * 4;

    for (int k0 = 0; k0 < K; k0 += 32) {
        // --- A tile: 128 x 32, row-major in, [row][k] out (tf32-rounded)
        #pragma unroll
        for (int i = 0; i < 4; i++) {
            int r = i * 32 + aRowStep;
            float4 v = *(const float4*)(A + (size_t)(bm + r) * K + k0 + aK4);
            float4 t;
            t.x = to_tf32(v.x); t.y = to_tf32(v.y);
            t.z = to_tf32(v.z); t.w = to_tf32(v.w);
            *(float4*)(&As[r][aK4]) = t;
        }
        // --- B tile: 32 x 128 in, transposed to [col][k]
        #pragma unroll
        for (int i = 0; i < 4; i++) {
            int kk = i * 8 + bKStep;
            float4 v = *(const float4*)(B + (size_t)(k0 + kk) * N + bn + bN4);
            Bs[bN4 + 0][kk] = to_tf32(v.x);
            Bs[bN4 + 1][kk] = to_tf32(v.y);
            Bs[bN4 + 2][kk] = to_tf32(v.z);
            Bs[bN4 + 3][kk] = to_tf32(v.w);
        }
        __syncthreads();

        #pragma unroll
        for (int ks = 0; ks < 4; ks++) {
            const int kb = ks * 8;
            uint32_t a[4][4], b[4][2];
            #pragma unroll
            for (int mf = 0; mf < 4; mf++) {
                int r = wm * 64 + mf * 16 + g;
                a[mf][0] = __float_as_uint(As[r    ][kb + tg    ]);
                a[mf][1] = __float_as_uint(As[r + 8][kb + tg    ]);
                a[mf][2] = __float_as_uint(As[r    ][kb + tg + 4]);
                a[mf][3] = __float_as_uint(As[r + 8][kb + tg + 4]);
            }
            #pragma unroll
            for (int nf = 0; nf < 4; nf++) {
                int n = wn * 32 + nf * 8 + g;
                b[nf][0] = __float_as_uint(Bs[n][kb + tg    ]);
                b[nf][1] = __float_as_uint(Bs[n][kb + tg + 4]);
            }
            #pragma unroll
            for (int mf = 0; mf < 4; mf++)
                #pragma unroll
                for (int nf = 0; nf < 4; nf++)
                    mma_tf32(acc[mf][nf][0], acc[mf][nf][1],
                             acc[mf][nf][2], acc[mf][nf][3],
                             a[mf][0], a[mf][1], a[mf][2], a[mf][3],
                             b[nf][0], b[nf][1]);
        }
        __syncthreads();
    }

    // --- epilogue ---
    #pragma unroll
    for (int mf = 0; mf < 4; mf++) {
        #pragma unroll
        for (int half = 0; half < 2; half++) {
            int row = bm + wm * 64 + mf * 16 + g + half * 8;
            size_t rbase = (size_t)row * N;
            size_t gbase = (size_t)(row >> 10) * SIXD;
            #pragma unroll
            for (int nf = 0; nf < 4; nf++) {
                int col = bn + wn * 32 + nf * 8 + 2 * tg;
                float y0 = acc[mf][nf][half * 2 + 0] + bias[col];
                float y1 = acc[mf][nf][half * 2 + 1] + bias[col + 1];
                if (EPI == 1) { y0 = gelu_tanh(y0); y1 = gelu_tanh(y1); }
                if (EPI == 2) {
                    y0 = res[rbase + col]     + gate[gbase + col]     * y0;
                    y1 = res[rbase + col + 1] + gate[gbase + col + 1] * y1;
                }
                C[rbase + col]     = y0;
                C[rbase + col + 1] = y1;
            }
        }
    }
}

// ---------------------------------------------------------------------------
// Kernel 4: flash attention, fp32, head dim 64, N=1024
// ---------------------------------------------------------------------------
#define ATTN_SMEM_FLOATS (4 * 64 * 65 + 3 * 64)

__global__ void __launch_bounds__(256) attn_kernel(
    const float* __restrict__ q, const float* __restrict__ kv,
    float* __restrict__ out)
{
    extern __shared__ float sm[];
    float (*Qs)[65] = reinterpret_cast<float(*)[65]>(sm);
    float (*Ks)[65] = reinterpret_cast<float(*)[65]>(sm + 64 * 65);
    float (*Vs)[65] = reinterpret_cast<float(*)[65]>(sm + 2 * 64 * 65);
    float (*Ss)[65] = reinterpret_cast<float(*)[65]>(sm + 3 * 64 * 65);
    float* rowM = sm + 4 * 64 * 65;
    float* rowL = rowM + 64;
    float* rowC = rowL + 64;

    const int tid = threadIdx.x;
    const int tx = tid & 15, ty = tid >> 4;
    const int bh = blockIdx.y;
    const int b = bh >> 4, h = bh & 15;
    const int q0 = blockIdx.x * 64;

    for (int t = tid; t < 64 * 16; t += 256) {
        int r = t >> 4, d4 = t & 15;
        float4 v = *(const float4*)(q +
            ((((size_t)(b * NTOK + q0 + r)) * HEADS + h) << 6) + d4 * 4);
        Qs[r][d4 * 4 + 0] = v.x; Qs[r][d4 * 4 + 1] = v.y;
        Qs[r][d4 * 4 + 2] = v.z; Qs[r][d4 * 4 + 3] = v.w;
    }
    if (tid < 64) { rowM[tid] = -INFINITY; rowL[tid] = 0.f; }

    float o[4][4];
    #pragma unroll
    for (int i = 0; i < 4; i++)
        #pragma unroll
        for (int j = 0; j < 4; j++) o[i][j] = 0.f;

    for (int jt = 0; jt < NTOK / 64; jt++) {
        int j0 = jt * 64;
        for (int t = tid; t < 64 * 16; t += 256) {
            int r = t >> 4, d4 = t & 15;
            size_t base = (size_t)(b * NTOK + j0 + r) * (2 * DMODEL) + h * HDIM + d4 * 4;
            float4 kvec = *(const float4*)(kv + base);
            float4 vvec = *(const float4*)(kv + base + DMODEL);
            Ks[r][d4 * 4 + 0] = kvec.x; Ks[r][d4 * 4 + 1] = kvec.y;
            Ks[r][d4 * 4 + 2] = kvec.z; Ks[r][d4 * 4 + 3] = kvec.w;
            Vs[r][d4 * 4 + 0] = vvec.x; Vs[r][d4 * 4 + 1] = vvec.y;
            Vs[r][d4 * 4 + 2] = vvec.z; Vs[r][d4 * 4 + 3] = vvec.w;
        }
        __syncthreads();

        float s4[4][4];
        #pragma unroll
        for (int i = 0; i < 4; i++)
            #pragma unroll
            for (int j = 0; j < 4; j++) s4[i][j] = 0.f;
        #pragma unroll 8
        for (int kk = 0; kk < 64; kk++) {
            float a[4], bb[4];
            #pragma unroll
            for (int i = 0; i < 4; i++) a[i] = Qs[ty * 4 + i][kk];
            #pragma unroll
            for (int j = 0; j < 4; j++) bb[j] = Ks[tx * 4 + j][kk];
            #pragma unroll
            for (int i = 0; i < 4; i++)
                #pragma unroll
                for (int j = 0; j < 4; j++)
                    s4[i][j] = fmaf(a[i], bb[j], s4[i][j]);
        }
        #pragma unroll
        for (int i = 0; i < 4; i++)
            #pragma unroll
            for (int j = 0; j < 4; j++)
                Ss[ty * 4 + i][tx * 4 + j] = s4[i][j] * ATTN_SCALE;
        __syncthreads();

        {
            int w = tid >> 5, lane = tid & 31;
            for (int rr = 0; rr < 8; rr++) {
                int r = w * 8 + rr;
                float v0 = Ss[r][lane], v1 = Ss[r][lane + 32];
                float mx = fmaxf(v0, v1);
                #pragma unroll
                for (int off = 16; off; off >>= 1)
                    mx = fmaxf(mx, __shfl_xor_sync(0xffffffffu, mx, off));
                float mOld = rowM[r];
                float mNew = fmaxf(mOld, mx);
                float p0 = __expf(v0 - mNew), p1 = __expf(v1 - mNew);
                float ssum = p0 + p1;
                #pragma unroll
                for (int off = 16; off; off >>= 1)
                    ssum += __shfl_xor_sync(0xffffffffu, ssum, off);
                Ss[r][lane] = p0; Ss[r][lane + 32] = p1;
                if (lane == 0) {
                    float corr = __expf(mOld - mNew);
                    rowC[r] = corr;
                    rowL[r] = rowL[r] * corr + ssum;
                    rowM[r] = mNew;
                }
            }
        }
        __syncthreads();

        float cf[4];
        #pragma unroll
        for (int i = 0; i < 4; i++) cf[i] = rowC[ty * 4 + i];
        #pragma unroll
        for (int i = 0; i < 4; i++)
            #pragma unroll
            for (int j = 0; j < 4; j++) o[i][j] *= cf[i];
        #pragma unroll 8
        for (int kk = 0; kk < 64; kk++) {
            float p[4], vv[4];
            #pragma unroll
            for (int i = 0; i < 4; i++) p[i] = Ss[ty * 4 + i][kk];
            #pragma unroll
            for (int j = 0; j < 4; j++) vv[j] = Vs[kk][tx * 4 + j];
            #pragma unroll
            for (int i = 0; i < 4; i++)
                #pragma unroll
                for (int j = 0; j < 4; j++)
                    o[i][j] = fmaf(p[i], vv[j], o[i][j]);
        }
        __syncthreads();
    }

    #pragma unroll
    for (int i = 0; i < 4; i++) {
        int qi = ty * 4 + i;
        float inv = 1.0f / rowL[qi];
        size_t base = (((size_t)(b * NTOK + q0 + qi)) * HEADS + h) << 6;
        #pragma unroll
        for (int j = 0; j < 4; j++)
            out[base + tx * 4 + j] = o[i][j] * inv;
    }
}

// ---------------------------------------------------------------------------
// Launch
// ---------------------------------------------------------------------------
extern "C" void kernel_launch(void* const* d_in, const int* in_sizes, int n_in,
                              void* d_out, int out_size)
{
    const float* x    = (const float*)d_in[0];
    const float* c    = (const float*)d_in[1];
    const float* Wq   = (const float*)d_in[2];
    const float* bq   = (const float*)d_in[3];
    const float* Wkv  = (const float*)d_in[4];
    const float* bkv  = (const float*)d_in[5];
    const float* Wo   = (const float*)d_in[6];
    const float* bo   = (const float*)d_in[7];
    const float* W1   = (const float*)d_in[8];
    const float* b1   = (const float*)d_in[9];
    const float* W2   = (const float*)d_in[10];
    const float* b2   = (const float*)d_in[11];
    const float* Wada = (const float*)d_in[12];
    const float* bada = (const float*)d_in[13];
    float* out = (float*)d_out;

    float *mod, *h, *q, *kv, *att, *m1;
    cudaGetSymbolAddress((void**)&mod, g_mod);
    cudaGetSymbolAddress((void**)&h,   g_h);
    cudaGetSymbolAddress((void**)&q,   g_q);
    cudaGetSymbolAddress((void**)&kv,  g_kv);
    cudaGetSymbolAddress((void**)&att, g_att);
    cudaGetSymbolAddress((void**)&m1,  g_m1);

    const int attnSmem = ATTN_SMEM_FLOATS * (int)sizeof(float);
    cudaFuncSetAttribute(attn_kernel,
                         cudaFuncAttributeMaxDynamicSharedMemorySize, attnSmem);

    // 1) adaLN modulation
    ada_mod_kernel<<<dim3(SIXD / 256, BATCH), 256>>>(c, Wada, bada, mod);

    // 2) h = modulate(LN(x), sh_msa, sc_msa)
    ln_mod_kernel<<<ROWS, 256>>>(x, mod, 0 * DMODEL, 1 * DMODEL, h);

    // 3) q = h @ Wq + bq ; kv = h @ Wkv + bkv
    mma_gemm_kernel<0><<<dim3(DMODEL / 128, ROWS / 128), 256>>>(
        h, Wq, bq, nullptr, nullptr, q, ROWS, DMODEL, DMODEL);
    mma_gemm_kernel<0><<<dim3(2 * DMODEL / 128, ROWS / 128), 256>>>(
        h, Wkv, bkv, nullptr, nullptr, kv, ROWS, 2 * DMODEL, DMODEL);

    // 4) attention
    attn_kernel<<<dim3(NTOK / 64, BATCH * HEADS), 256, attnSmem>>>(q, kv, att);

    // 5) x1 = x + g_msa * (att @ Wo + bo)   -> d_out
    mma_gemm_kernel<2><<<dim3(DMODEL / 128, ROWS / 128), 256>>>(
        att, Wo, bo, x, mod + 2 * DMODEL, out, ROWS, DMODEL, DMODEL);

    // 6) h2 = modulate(LN(x1), sh_mlp, sc_mlp)
    ln_mod_kernel<<<ROWS, 256>>>(out, mod, 3 * DMODEL, 4 * DMODEL, h);

    // 7) m1 = gelu(h2 @ W1 + b1)
    mma_gemm_kernel<1><<<dim3(MLPD / 128, ROWS / 128), 256>>>(
        h, W1, b1, nullptr, nullptr, m1, ROWS, MLPD, DMODEL);

    // 8) x2 = x1 + g_mlp * (m1 @ W2 + b2)   -> d_out
    mma_gemm_kernel<2><<<dim3(DMODEL / 128, ROWS / 128), 256>>>(
        m1, W2, b2, out, mod + 5 * DMODEL, out, ROWS, DMODEL, MLPD);
}

// round 5
// speedup vs baseline: 2.3053x; 1.5882x over previous
#include <cuda_runtime.h>
#include <math.h>
#include <stdint.h>

// ---------------------------------------------------------------------------
// Problem constants
// ---------------------------------------------------------------------------
#define BATCH  4
#define NTOK   1024
#define DMODEL 1024
#define HEADS  16
#define HDIM   64
#define ROWS   (BATCH * NTOK)     // 4096
#define MLPD   4096
#define SIXD   (6 * DMODEL)       // 6144
#define EPS    1e-6f
#define ATTN_SCALE 0.125f         // 64^-0.5

// ---------------------------------------------------------------------------
// Scratch (device globals: no allocations allowed)
// ---------------------------------------------------------------------------
__device__ float g_mod[BATCH * SIXD];
__device__ float g_h  [ROWS * DMODEL];
__device__ float g_q  [ROWS * DMODEL];
__device__ float g_kv [ROWS * 2 * DMODEL];
__device__ float g_att[ROWS * DMODEL];
__device__ float g_m1 [ROWS * MLPD];

// ---------------------------------------------------------------------------
// Helpers
// ---------------------------------------------------------------------------
__device__ __forceinline__ float gelu_tanh(float y) {
    float y3 = y * y * y;
    return 0.5f * y * (1.0f + tanhf(0.7978845608028654f * (y + 0.044715f * y3)));
}

__device__ __forceinline__ void cp_async16(void* smem_dst, const void* gmem_src) {
    uint32_t s = (uint32_t)__cvta_generic_to_shared(smem_dst);
    asm volatile("cp.async.cg.shared.global [%0], [%1], 16;\n"
                 :: "r"(s), "l"(gmem_src));
}
__device__ __forceinline__ void cp_commit() {
    asm volatile("cp.async.commit_group;\n");
}
template <int N>
__device__ __forceinline__ void cp_wait() {
    asm volatile("cp.async.wait_group %0;\n" :: "n"(N));
}

__device__ __forceinline__ void mma_tf32(
    float& d0, float& d1, float& d2, float& d3,
    uint32_t a0, uint32_t a1, uint32_t a2, uint32_t a3,
    uint32_t b0, uint32_t b1)
{
    asm volatile(
        "mma.sync.aligned.m16n8k8.row.col.f32.tf32.tf32.f32 "
        "{%0,%1,%2,%3}, {%4,%5,%6,%7}, {%8,%9}, {%0,%1,%2,%3};"
        : "+f"(d0), "+f"(d1), "+f"(d2), "+f"(d3)
        : "r"(a0), "r"(a1), "r"(a2), "r"(a3), "r"(b0), "r"(b1));
}

// ---------------------------------------------------------------------------
// Kernel 1: mod = silu(c) @ Wada + bada        [4, 6144]
// ---------------------------------------------------------------------------
__global__ void __launch_bounds__(256) ada_mod_kernel(
    const float* __restrict__ c, const float* __restrict__ Wada,
    const float* __restrict__ bada, float* __restrict__ mod)
{
    __shared__ float sc[DMODEL];
    int b = blockIdx.y;
    int n = blockIdx.x * 256 + threadIdx.x;
    for (int i = threadIdx.x; i < DMODEL; i += 256) {
        float v = c[b * DMODEL + i];
        sc[i] = v / (1.0f + __expf(-v));
    }
    __syncthreads();
    float acc = 0.0f;
    const float* wp = Wada + n;
    for (int k = 0; k < DMODEL; k++)
        acc = fmaf(sc[k], wp[(size_t)k * SIXD], acc);
    mod[b * SIXD + n] = acc + bada[n];
}

// ---------------------------------------------------------------------------
// Kernel 2: out = LN(x) * (1 + scale) + shift, per row (D=1024)
// ---------------------------------------------------------------------------
__global__ void __launch_bounds__(256) ln_mod_kernel(
    const float* __restrict__ x, const float* __restrict__ mod,
    int shiftOff, int scaleOff, float* __restrict__ out)
{
    __shared__ float red[8];
    int row = blockIdx.x;
    int b = row >> 10;
    const float4* xr = (const float4*)(x + (size_t)row * DMODEL);
    float4 v = xr[threadIdx.x];

    float s = v.x + v.y + v.z + v.w;
    #pragma unroll
    for (int o = 16; o; o >>= 1) s += __shfl_xor_sync(0xffffffffu, s, o);
    if ((threadIdx.x & 31) == 0) red[threadIdx.x >> 5] = s;
    __syncthreads();
    float tot = 0.f;
    #pragma unroll
    for (int w = 0; w < 8; w++) tot += red[w];
    float mean = tot * (1.0f / DMODEL);
    __syncthreads();

    float dx = v.x - mean, dy = v.y - mean, dz = v.z - mean, dw = v.w - mean;
    float q = dx * dx + dy * dy + dz * dz + dw * dw;
    #pragma unroll
    for (int o = 16; o; o >>= 1) q += __shfl_xor_sync(0xffffffffu, q, o);
    if ((threadIdx.x & 31) == 0) red[threadIdx.x >> 5] = q;
    __syncthreads();
    float vtot = 0.f;
    #pragma unroll
    for (int w = 0; w < 8; w++) vtot += red[w];
    float rstd = rsqrtf(vtot * (1.0f / DMODEL) + EPS);

    int c0 = threadIdx.x * 4;
    const float* base = mod + (size_t)b * SIXD;
    float4 shv = *(const float4*)(base + shiftOff + c0);
    float4 scv = *(const float4*)(base + scaleOff + c0);
    float4 r;
    r.x = dx * rstd * (1.0f + scv.x) + shv.x;
    r.y = dy * rstd * (1.0f + scv.y) + shv.y;
    r.z = dz * rstd * (1.0f + scv.z) + shv.z;
    r.w = dw * rstd * (1.0f + scv.w) + shv.w;
    ((float4*)(out + (size_t)row * DMODEL))[threadIdx.x] = r;
}

// ---------------------------------------------------------------------------
// Kernel 3: TF32 tensor-core GEMM with cp.async 3-stage pipeline
//   C[M,N] = A[M,K] @ B[K,N] (+ epilogue)
//   EPI 0: C = acc + bias[n]
//   EPI 1: C = gelu(acc + bias[n])
//   EPI 2: C = res[m,n] + gate[(m>>10)*6144 + n] * (acc + bias[n])
// Block tile 128x128x32, 8 warps (2m x 4n), warp tile 64x32.
// A staged as [row][36] (pad: banks g*4+tg), B as [k][136] (banks tg*8+g).
// fp32 bits fed to tf32 mma directly (HW truncation; ~<=2x RNA error).
// ---------------------------------------------------------------------------
#define GSTAGES 3
#define APAD 36
#define BPAD 136
#define GEMM_SMEM_BYTES (GSTAGES * (128 * APAD + 32 * BPAD) * (int)sizeof(float))

template <int EPI>
__global__ void __launch_bounds__(256, 2) mma_gemm_kernel(
    const float* __restrict__ A, const float* __restrict__ B,
    const float* __restrict__ bias, const float* __restrict__ res,
    const float* __restrict__ gate, float* __restrict__ C,
    int M, int N, int K)
{
    extern __shared__ char smemRaw[];
    float (*As)[128][APAD] = reinterpret_cast<float(*)[128][APAD]>(smemRaw);
    float (*Bs)[32][BPAD]  = reinterpret_cast<float(*)[32][BPAD]>(
        smemRaw + GSTAGES * 128 * APAD * sizeof(float));

    const int tid  = threadIdx.x;
    const int lane = tid & 31;
    const int warp = tid >> 5;
    const int wm   = warp & 1;      // 0..1 -> 64-row band
    const int wn   = warp >> 1;     // 0..3 -> 32-col band
    const int bm   = blockIdx.y * 128;
    const int bn   = blockIdx.x * 128;

    const int g  = lane >> 2;       // group id 0..7
    const int tg = lane & 3;        // thread-in-group 0..3

    // async-copy indices (16B chunks)
    const int aRow0 = tid >> 3;          // chunk row base (A: 8 chunks/row)
    const int aK4   = (tid & 7) * 4;     // k offset
    const int bK0   = tid >> 5;          // chunk k base  (B: 32 chunks/row)
    const int bN4   = (tid & 31) * 4;    // n offset

    float acc[4][4][4];
    #pragma unroll
    for (int i = 0; i < 4; i++)
        #pragma unroll
        for (int j = 0; j < 4; j++)
            #pragma unroll
            for (int r = 0; r < 4; r++) acc[i][j][r] = 0.f;

    const int kTiles = K >> 5;   // K / 32

    // tile loader: stage st, k-offset k0
    auto load_tile = [&](int st, int k0) {
        #pragma unroll
        for (int i = 0; i < 4; i++) {
            int r = i * 32 + aRow0;
            cp_async16(&As[st][r][aK4],
                       A + (size_t)(bm + r) * K + k0 + aK4);
        }
        #pragma unroll
        for (int i = 0; i < 4; i++) {
            int kk = i * 8 + bK0;
            cp_async16(&Bs[st][kk][bN4],
                       B + (size_t)(k0 + kk) * N + bn + bN4);
        }
    };

    // prologue: stages 0..GSTAGES-2
    #pragma unroll
    for (int s = 0; s < GSTAGES - 1; s++) {
        load_tile(s, s * 32);
        cp_commit();
    }

    for (int it = 0; it < kTiles; it++) {
        cp_wait<GSTAGES - 2>();
        __syncthreads();

        int nxt = it + GSTAGES - 1;
        if (nxt < kTiles)
            load_tile(nxt % GSTAGES, nxt * 32);
        cp_commit();

        const int st = it % GSTAGES;
        #pragma unroll
        for (int ks = 0; ks < 4; ks++) {
            const int kb = ks * 8;
            uint32_t a[4][4], b[4][2];
            #pragma unroll
            for (int mf = 0; mf < 4; mf++) {
                int r = wm * 64 + mf * 16 + g;
                a[mf][0] = __float_as_uint(As[st][r    ][kb + tg    ]);
                a[mf][1] = __float_as_uint(As[st][r + 8][kb + tg    ]);
                a[mf][2] = __float_as_uint(As[st][r    ][kb + tg + 4]);
                a[mf][3] = __float_as_uint(As[st][r + 8][kb + tg + 4]);
            }
            #pragma unroll
            for (int nf = 0; nf < 4; nf++) {
                int n = wn * 32 + nf * 8 + g;
                b[nf][0] = __float_as_uint(Bs[st][kb + tg    ][n]);
                b[nf][1] = __float_as_uint(Bs[st][kb + tg + 4][n]);
            }
            #pragma unroll
            for (int mf = 0; mf < 4; mf++)
                #pragma unroll
                for (int nf = 0; nf < 4; nf++)
                    mma_tf32(acc[mf][nf][0], acc[mf][nf][1],
                             acc[mf][nf][2], acc[mf][nf][3],
                             a[mf][0], a[mf][1], a[mf][2], a[mf][3],
                             b[nf][0], b[nf][1]);
        }
        __syncthreads();
    }

    // --- epilogue ---
    #pragma unroll
    for (int mf = 0; mf < 4; mf++) {
        #pragma unroll
        for (int half = 0; half < 2; half++) {
            int row = bm + wm * 64 + mf * 16 + g + half * 8;
            size_t rbase = (size_t)row * N;
            size_t gbase = (size_t)(row >> 10) * SIXD;
            #pragma unroll
            for (int nf = 0; nf < 4; nf++) {
                int col = bn + wn * 32 + nf * 8 + 2 * tg;
                float y0 = acc[mf][nf][half * 2 + 0] + bias[col];
                float y1 = acc[mf][nf][half * 2 + 1] + bias[col + 1];
                if (EPI == 1) { y0 = gelu_tanh(y0); y1 = gelu_tanh(y1); }
                if (EPI == 2) {
                    y0 = res[rbase + col]     + gate[gbase + col]     * y0;
                    y1 = res[rbase + col + 1] + gate[gbase + col + 1] * y1;
                }
                C[rbase + col]     = y0;
                C[rbase + col + 1] = y1;
            }
        }
    }
}

// ---------------------------------------------------------------------------
// Kernel 4: flash attention, fp32, head dim 64, N=1024
// ---------------------------------------------------------------------------
#define ATTN_SMEM_FLOATS (4 * 64 * 65 + 3 * 64)

__global__ void __launch_bounds__(256) attn_kernel(
    const float* __restrict__ q, const float* __restrict__ kv,
    float* __restrict__ out)
{
    extern __shared__ float sm[];
    float (*Qs)[65] = reinterpret_cast<float(*)[65]>(sm);
    float (*Ks)[65] = reinterpret_cast<float(*)[65]>(sm + 64 * 65);
    float (*Vs)[65] = reinterpret_cast<float(*)[65]>(sm + 2 * 64 * 65);
    float (*Ss)[65] = reinterpret_cast<float(*)[65]>(sm + 3 * 64 * 65);
    float* rowM = sm + 4 * 64 * 65;
    float* rowL = rowM + 64;
    float* rowC = rowL + 64;

    const int tid = threadIdx.x;
    const int tx = tid & 15, ty = tid >> 4;
    const int bh = blockIdx.y;
    const int b = bh >> 4, h = bh & 15;
    const int q0 = blockIdx.x * 64;

    for (int t = tid; t < 64 * 16; t += 256) {
        int r = t >> 4, d4 = t & 15;
        float4 v = *(const float4*)(q +
            ((((size_t)(b * NTOK + q0 + r)) * HEADS + h) << 6) + d4 * 4);
        Qs[r][d4 * 4 + 0] = v.x; Qs[r][d4 * 4 + 1] = v.y;
        Qs[r][d4 * 4 + 2] = v.z; Qs[r][d4 * 4 + 3] = v.w;
    }
    if (tid < 64) { rowM[tid] = -INFINITY; rowL[tid] = 0.f; }

    float o[4][4];
    #pragma unroll
    for (int i = 0; i < 4; i++)
        #pragma unroll
        for (int j = 0; j < 4; j++) o[i][j] = 0.f;

    for (int jt = 0; jt < NTOK / 64; jt++) {
        int j0 = jt * 64;
        for (int t = tid; t < 64 * 16; t += 256) {
            int r = t >> 4, d4 = t & 15;
            size_t base = (size_t)(b * NTOK + j0 + r) * (2 * DMODEL) + h * HDIM + d4 * 4;
            float4 kvec = *(const float4*)(kv + base);
            float4 vvec = *(const float4*)(kv + base + DMODEL);
            Ks[r][d4 * 4 + 0] = kvec.x; Ks[r][d4 * 4 + 1] = kvec.y;
            Ks[r][d4 * 4 + 2] = kvec.z; Ks[r][d4 * 4 + 3] = kvec.w;
            Vs[r][d4 * 4 + 0] = vvec.x; Vs[r][d4 * 4 + 1] = vvec.y;
            Vs[r][d4 * 4 + 2] = vvec.z; Vs[r][d4 * 4 + 3] = vvec.w;
        }
        __syncthreads();

        float s4[4][4];
        #pragma unroll
        for (int i = 0; i < 4; i++)
            #pragma unroll
            for (int j = 0; j < 4; j++) s4[i][j] = 0.f;
        #pragma unroll 8
        for (int kk = 0; kk < 64; kk++) {
            float a[4], bb[4];
            #pragma unroll
            for (int i = 0; i < 4; i++) a[i] = Qs[ty * 4 + i][kk];
            #pragma unroll
            for (int j = 0; j < 4; j++) bb[j] = Ks[tx * 4 + j][kk];
            #pragma unroll
            for (int i = 0; i < 4; i++)
                #pragma unroll
                for (int j = 0; j < 4; j++)
                    s4[i][j] = fmaf(a[i], bb[j], s4[i][j]);
        }
        #pragma unroll
        for (int i = 0; i < 4; i++)
            #pragma unroll
            for (int j = 0; j < 4; j++)
                Ss[ty * 4 + i][tx * 4 + j] = s4[i][j] * ATTN_SCALE;
        __syncthreads();

        {
            int w = tid >> 5, lane = tid & 31;
            for (int rr = 0; rr < 8; rr++) {
                int r = w * 8 + rr;
                float v0 = Ss[r][lane], v1 = Ss[r][lane + 32];
                float mx = fmaxf(v0, v1);
                #pragma unroll
                for (int off = 16; off; off >>= 1)
                    mx = fmaxf(mx, __shfl_xor_sync(0xffffffffu, mx, off));
                float mOld = rowM[r];
                float mNew = fmaxf(mOld, mx);
                float p0 = __expf(v0 - mNew), p1 = __expf(v1 - mNew);
                float ssum = p0 + p1;
                #pragma unroll
                for (int off = 16; off; off >>= 1)
                    ssum += __shfl_xor_sync(0xffffffffu, ssum, off);
                Ss[r][lane] = p0; Ss[r][lane + 32] = p1;
                if (lane == 0) {
                    float corr = __expf(mOld - mNew);
                    rowC[r] = corr;
                    rowL[r] = rowL[r] * corr + ssum;
                    rowM[r] = mNew;
                }
            }
        }
        __syncthreads();

        float cf[4];
        #pragma unroll
        for (int i = 0; i < 4; i++) cf[i] = rowC[ty * 4 + i];
        #pragma unroll
        for (int i = 0; i < 4; i++)
            #pragma unroll
            for (int j = 0; j < 4; j++) o[i][j] *= cf[i];
        #pragma unroll 8
        for (int kk = 0; kk < 64; kk++) {
            float p[4], vv[4];
            #pragma unroll
            for (int i = 0; i < 4; i++) p[i] = Ss[ty * 4 + i][kk];
            #pragma unroll
            for (int j = 0; j < 4; j++) vv[j] = Vs[kk][tx * 4 + j];
            #pragma unroll
            for (int i = 0; i < 4; i++)
                #pragma unroll
                for (int j = 0; j < 4; j++)
                    o[i][j] = fmaf(p[i], vv[j], o[i][j]);
        }
        __syncthreads();
    }

    #pragma unroll
    for (int i = 0; i < 4; i++) {
        int qi = ty * 4 + i;
        float inv = 1.0f / rowL[qi];
        size_t base = (((size_t)(b * NTOK + q0 + qi)) * HEADS + h) << 6;
        #pragma unroll
        for (int j = 0; j < 4; j++)
            out[base + tx * 4 + j] = o[i][j] * inv;
    }
}

// ---------------------------------------------------------------------------
// Launch
// ---------------------------------------------------------------------------
extern "C" void kernel_launch(void* const* d_in, const int* in_sizes, int n_in,
                              void* d_out, int out_size)
{
    const float* x    = (const float*)d_in[0];
    const float* c    = (const float*)d_in[1];
    const float* Wq   = (const float*)d_in[2];
    const float* bq   = (const float*)d_in[3];
    const float* Wkv  = (const float*)d_in[4];
    const float* bkv  = (const float*)d_in[5];
    const float* Wo   = (const float*)d_in[6];
    const float* bo   = (const float*)d_in[7];
    const float* W1   = (const float*)d_in[8];
    const float* b1   = (const float*)d_in[9];
    const float* W2   = (const float*)d_in[10];
    const float* b2   = (const float*)d_in[11];
    const float* Wada = (const float*)d_in[12];
    const float* bada = (const float*)d_in[13];
    float* out = (float*)d_out;

    float *mod, *h, *q, *kv, *att, *m1;
    cudaGetSymbolAddress((void**)&mod, g_mod);
    cudaGetSymbolAddress((void**)&h,   g_h);
    cudaGetSymbolAddress((void**)&q,   g_q);
    cudaGetSymbolAddress((void**)&kv,  g_kv);
    cudaGetSymbolAddress((void**)&att, g_att);
    cudaGetSymbolAddress((void**)&m1,  g_m1);

    const int attnSmem = ATTN_SMEM_FLOATS * (int)sizeof(float);
    cudaFuncSetAttribute(attn_kernel,
                         cudaFuncAttributeMaxDynamicSharedMemorySize, attnSmem);
    cudaFuncSetAttribute(mma_gemm_kernel<0>,
                         cudaFuncAttributeMaxDynamicSharedMemorySize, GEMM_SMEM_BYTES);
    cudaFuncSetAttribute(mma_gemm_kernel<1>,
                         cudaFuncAttributeMaxDynamicSharedMemorySize, GEMM_SMEM_BYTES);
    cudaFuncSetAttribute(mma_gemm_kernel<2>,
                         cudaFuncAttributeMaxDynamicSharedMemorySize, GEMM_SMEM_BYTES);

    // 1) adaLN modulation
    ada_mod_kernel<<<dim3(SIXD / 256, BATCH), 256>>>(c, Wada, bada, mod);

    // 2) h = modulate(LN(x), sh_msa, sc_msa)
    ln_mod_kernel<<<ROWS, 256>>>(x, mod, 0 * DMODEL, 1 * DMODEL, h);

    // 3) q = h @ Wq + bq ; kv = h @ Wkv + bkv
    mma_gemm_kernel<0><<<dim3(DMODEL / 128, ROWS / 128), 256, GEMM_SMEM_BYTES>>>(
        h, Wq, bq, nullptr, nullptr, q, ROWS, DMODEL, DMODEL);
    mma_gemm_kernel<0><<<dim3(2 * DMODEL / 128, ROWS / 128), 256, GEMM_SMEM_BYTES>>>(
        h, Wkv, bkv, nullptr, nullptr, kv, ROWS, 2 * DMODEL, DMODEL);

    // 4) attention
    attn_kernel<<<dim3(NTOK / 64, BATCH * HEADS), 256, attnSmem>>>(q, kv, att);

    // 5) x1 = x + g_msa * (att @ Wo + bo)   -> d_out
    mma_gemm_kernel<2><<<dim3(DMODEL / 128, ROWS / 128), 256, GEMM_SMEM_BYTES>>>(
        att, Wo, bo, x, mod + 2 * DMODEL, out, ROWS, DMODEL, DMODEL);

    // 6) h2 = modulate(LN(x1), sh_mlp, sc_mlp)
    ln_mod_kernel<<<ROWS, 256>>>(out, mod, 3 * DMODEL, 4 * DMODEL, h);

    // 7) m1 = gelu(h2 @ W1 + b1)
    mma_gemm_kernel<1><<<dim3(MLPD / 128, ROWS / 128), 256, GEMM_SMEM_BYTES>>>(
        h, W1, b1, nullptr, nullptr, m1, ROWS, MLPD, DMODEL);

    // 8) x2 = x1 + g_mlp * (m1 @ W2 + b2)   -> d_out
    mma_gemm_kernel<2><<<dim3(DMODEL / 128, ROWS / 128), 256, GEMM_SMEM_BYTES>>>(
        m1, W2, b2, out, mod + 5 * DMODEL, out, ROWS, DMODEL, MLPD);
}

// round 6
// speedup vs baseline: 3.2539x; 1.4114x over previous
#include <cuda_runtime.h>
#include <math.h>
#include <stdint.h>

// ---------------------------------------------------------------------------
// Problem constants
// ---------------------------------------------------------------------------
#define BATCH  4
#define NTOK   1024
#define DMODEL 1024
#define HEADS  16
#define HDIM   64
#define ROWS   (BATCH * NTOK)     // 4096
#define MLPD   4096
#define SIXD   (6 * DMODEL)       // 6144
#define EPS    1e-6f

// ---------------------------------------------------------------------------
// Scratch (device globals: no allocations allowed)
// ---------------------------------------------------------------------------
__device__ float g_mod[BATCH * SIXD];
__device__ float g_h  [ROWS * DMODEL];
__device__ float g_q  [ROWS * DMODEL];
__device__ float g_kv [ROWS * 2 * DMODEL];
__device__ float g_att[ROWS * DMODEL];
__device__ float g_m1 [ROWS * MLPD];
// tf32-rounded weight copies
__device__ float g_wq [DMODEL * DMODEL];
__device__ float g_wkv[DMODEL * 2 * DMODEL];
__device__ float g_wo [DMODEL * DMODEL];
__device__ float g_w1 [DMODEL * MLPD];
__device__ float g_w2 [MLPD * DMODEL];

// ---------------------------------------------------------------------------
// Helpers
// ---------------------------------------------------------------------------
__device__ __forceinline__ float gelu_tanh(float y) {
    float y3 = y * y * y;
    return 0.5f * y * (1.0f + tanhf(0.7978845608028654f * (y + 0.044715f * y3)));
}

__device__ __forceinline__ float to_tf32(float x) {
    uint32_t y;
    asm("cvt.rna.tf32.f32 %0, %1;" : "=r"(y) : "f"(x));
    return __uint_as_float(y);
}

__device__ __forceinline__ void cp_async16(void* smem_dst, const void* gmem_src) {
    uint32_t s = (uint32_t)__cvta_generic_to_shared(smem_dst);
    asm volatile("cp.async.cg.shared.global [%0], [%1], 16;\n"
                 :: "r"(s), "l"(gmem_src));
}
__device__ __forceinline__ void cp_commit() {
    asm volatile("cp.async.commit_group;\n");
}
template <int N>
__device__ __forceinline__ void cp_wait() {
    asm volatile("cp.async.wait_group %0;\n" :: "n"(N));
}

__device__ __forceinline__ void mma_tf32(
    float& d0, float& d1, float& d2, float& d3,
    uint32_t a0, uint32_t a1, uint32_t a2, uint32_t a3,
    uint32_t b0, uint32_t b1)
{
    asm volatile(
        "mma.sync.aligned.m16n8k8.row.col.f32.tf32.tf32.f32 "
        "{%0,%1,%2,%3}, {%4,%5,%6,%7}, {%8,%9}, {%0,%1,%2,%3};"
        : "+f"(d0), "+f"(d1), "+f"(d2), "+f"(d3)
        : "r"(a0), "r"(a1), "r"(a2), "r"(a3), "r"(b0), "r"(b1));
}

// ---------------------------------------------------------------------------
// Kernel 0: round an fp32 array to tf32 (RNA), float4-vectorized
// ---------------------------------------------------------------------------
__global__ void __launch_bounds__(256) round_tf32_kernel(
    const float4* __restrict__ src, float4* __restrict__ dst, int n4)
{
    int i = blockIdx.x * 256 + threadIdx.x;
    if (i < n4) {
        float4 v = src[i];
        v.x = to_tf32(v.x); v.y = to_tf32(v.y);
        v.z = to_tf32(v.z); v.w = to_tf32(v.w);
        dst[i] = v;
    }
}

// ---------------------------------------------------------------------------
// Kernel 1: mod = silu(c) @ Wada + bada        [4, 6144]
// ---------------------------------------------------------------------------
__global__ void __launch_bounds__(256) ada_mod_kernel(
    const float* __restrict__ c, const float* __restrict__ Wada,
    const float* __restrict__ bada, float* __restrict__ mod)
{
    __shared__ float sc[DMODEL];
    int b = blockIdx.y;
    int n = blockIdx.x * 256 + threadIdx.x;
    for (int i = threadIdx.x; i < DMODEL; i += 256) {
        float v = c[b * DMODEL + i];
        sc[i] = v / (1.0f + __expf(-v));
    }
    __syncthreads();
    float acc = 0.0f;
    const float* wp = Wada + n;
    for (int k = 0; k < DMODEL; k++)
        acc = fmaf(sc[k], wp[(size_t)k * SIXD], acc);
    mod[b * SIXD + n] = acc + bada[n];
}

// ---------------------------------------------------------------------------
// Kernel 2: out = tf32(LN(x) * (1 + scale) + shift)   (output feeds GEMMs)
// ---------------------------------------------------------------------------
__global__ void __launch_bounds__(256) ln_mod_kernel(
    const float* __restrict__ x, const float* __restrict__ mod,
    int shiftOff, int scaleOff, float* __restrict__ out)
{
    __shared__ float red[8];
    int row = blockIdx.x;
    int b = row >> 10;
    const float4* xr = (const float4*)(x + (size_t)row * DMODEL);
    float4 v = xr[threadIdx.x];

    float s = v.x + v.y + v.z + v.w;
    #pragma unroll
    for (int o = 16; o; o >>= 1) s += __shfl_xor_sync(0xffffffffu, s, o);
    if ((threadIdx.x & 31) == 0) red[threadIdx.x >> 5] = s;
    __syncthreads();
    float tot = 0.f;
    #pragma unroll
    for (int w = 0; w < 8; w++) tot += red[w];
    float mean = tot * (1.0f / DMODEL);
    __syncthreads();

    float dx = v.x - mean, dy = v.y - mean, dz = v.z - mean, dw = v.w - mean;
    float q = dx * dx + dy * dy + dz * dz + dw * dw;
    #pragma unroll
    for (int o = 16; o; o >>= 1) q += __shfl_xor_sync(0xffffffffu, q, o);
    if ((threadIdx.x & 31) == 0) red[threadIdx.x >> 5] = q;
    __syncthreads();
    float vtot = 0.f;
    #pragma unroll
    for (int w = 0; w < 8; w++) vtot += red[w];
    float rstd = rsqrtf(vtot * (1.0f / DMODEL) + EPS);

    int c0 = threadIdx.x * 4;
    const float* base = mod + (size_t)b * SIXD;
    float4 shv = *(const float4*)(base + shiftOff + c0);
    float4 scv = *(const float4*)(base + scaleOff + c0);
    float4 r;
    r.x = to_tf32(dx * rstd * (1.0f + scv.x) + shv.x);
    r.y = to_tf32(dy * rstd * (1.0f + scv.y) + shv.y);
    r.z = to_tf32(dz * rstd * (1.0f + scv.z) + shv.z);
    r.w = to_tf32(dw * rstd * (1.0f + scv.w) + shv.w);
    ((float4*)(out + (size_t)row * DMODEL))[threadIdx.x] = r;
}

// ---------------------------------------------------------------------------
// Kernel 3: TF32 tensor-core GEMM with cp.async 3-stage pipeline
//   EPI 0: C = tf32(acc + bias[n])            (feeds attention mma)
//   EPI 1: C = tf32(gelu(acc + bias[n]))      (feeds W2 GEMM)
//   EPI 2: C = res + gate * (acc + bias[n])   (residual: exact fp32)
// Inputs are pre-rounded tf32, so in-mma truncation is the identity.
// ---------------------------------------------------------------------------
#define GSTAGES 3
#define APAD 36
#define BPAD 136
#define GEMM_SMEM_BYTES (GSTAGES * (128 * APAD + 32 * BPAD) * (int)sizeof(float))

template <int EPI>
__global__ void __launch_bounds__(256, 2) mma_gemm_kernel(
    const float* __restrict__ A, const float* __restrict__ B,
    const float* __restrict__ bias, const float* __restrict__ res,
    const float* __restrict__ gate, float* __restrict__ C,
    int M, int N, int K)
{
    extern __shared__ char smemRaw[];
    float (*As)[128][APAD] = reinterpret_cast<float(*)[128][APAD]>(smemRaw);
    float (*Bs)[32][BPAD]  = reinterpret_cast<float(*)[32][BPAD]>(
        smemRaw + GSTAGES * 128 * APAD * sizeof(float));

    const int tid  = threadIdx.x;
    const int lane = tid & 31;
    const int warp = tid >> 5;
    const int wm   = warp & 1;
    const int wn   = warp >> 1;
    const int bm   = blockIdx.y * 128;
    const int bn   = blockIdx.x * 128;

    const int g  = lane >> 2;
    const int tg = lane & 3;

    const int aRow0 = tid >> 3;
    const int aK4   = (tid & 7) * 4;
    const int bK0   = tid >> 5;
    const int bN4   = (tid & 31) * 4;

    float acc[4][4][4];
    #pragma unroll
    for (int i = 0; i < 4; i++)
        #pragma unroll
        for (int j = 0; j < 4; j++)
            #pragma unroll
            for (int r = 0; r < 4; r++) acc[i][j][r] = 0.f;

    const int kTiles = K >> 5;

    auto load_tile = [&](int st, int k0) {
        #pragma unroll
        for (int i = 0; i < 4; i++) {
            int r = i * 32 + aRow0;
            cp_async16(&As[st][r][aK4], A + (size_t)(bm + r) * K + k0 + aK4);
        }
        #pragma unroll
        for (int i = 0; i < 4; i++) {
            int kk = i * 8 + bK0;
            cp_async16(&Bs[st][kk][bN4], B + (size_t)(k0 + kk) * N + bn + bN4);
        }
    };

    #pragma unroll
    for (int s = 0; s < GSTAGES - 1; s++) {
        load_tile(s, s * 32);
        cp_commit();
    }

    for (int it = 0; it < kTiles; it++) {
        cp_wait<GSTAGES - 2>();
        __syncthreads();

        int nxt = it + GSTAGES - 1;
        if (nxt < kTiles)
            load_tile(nxt % GSTAGES, nxt * 32);
        cp_commit();

        const int st = it % GSTAGES;
        #pragma unroll
        for (int ks = 0; ks < 4; ks++) {
            const int kb = ks * 8;
            uint32_t a[4][4], b[4][2];
            #pragma unroll
            for (int mf = 0; mf < 4; mf++) {
                int r = wm * 64 + mf * 16 + g;
                a[mf][0] = __float_as_uint(As[st][r    ][kb + tg    ]);
                a[mf][1] = __float_as_uint(As[st][r + 8][kb + tg    ]);
                a[mf][2] = __float_as_uint(As[st][r    ][kb + tg + 4]);
                a[mf][3] = __float_as_uint(As[st][r + 8][kb + tg + 4]);
            }
            #pragma unroll
            for (int nf = 0; nf < 4; nf++) {
                int n = wn * 32 + nf * 8 + g;
                b[nf][0] = __float_as_uint(Bs[st][kb + tg    ][n]);
                b[nf][1] = __float_as_uint(Bs[st][kb + tg + 4][n]);
            }
            #pragma unroll
            for (int mf = 0; mf < 4; mf++)
                #pragma unroll
                for (int nf = 0; nf < 4; nf++)
                    mma_tf32(acc[mf][nf][0], acc[mf][nf][1],
                             acc[mf][nf][2], acc[mf][nf][3],
                             a[mf][0], a[mf][1], a[mf][2], a[mf][3],
                             b[nf][0], b[nf][1]);
        }
        __syncthreads();
    }

    #pragma unroll
    for (int mf = 0; mf < 4; mf++) {
        #pragma unroll
        for (int half = 0; half < 2; half++) {
            int row = bm + wm * 64 + mf * 16 + g + half * 8;
            size_t rbase = (size_t)row * N;
            size_t gbase = (size_t)(row >> 10) * SIXD;
            #pragma unroll
            for (int nf = 0; nf < 4; nf++) {
                int col = bn + wn * 32 + nf * 8 + 2 * tg;
                float y0 = acc[mf][nf][half * 2 + 0] + bias[col];
                float y1 = acc[mf][nf][half * 2 + 1] + bias[col + 1];
                if (EPI == 0) { y0 = to_tf32(y0); y1 = to_tf32(y1); }
                if (EPI == 1) { y0 = to_tf32(gelu_tanh(y0)); y1 = to_tf32(gelu_tanh(y1)); }
                if (EPI == 2) {
                    y0 = res[rbase + col]     + gate[gbase + col]     * y0;
                    y1 = res[rbase + col + 1] + gate[gbase + col + 1] * y1;
                }
                C[rbase + col]     = y0;
                C[rbase + col + 1] = y1;
            }
        }
    }
}

// ---------------------------------------------------------------------------
// Kernel 4: flash attention on tf32 tensor cores
// 8 warps x m16 = 128 q rows per block, Bc=64, d=64.
// QK^T and PV both mma.m16n8k8. Softmax in registers (row = one 4-lane quad).
// P round-trips through smem with RNA rounding. Scale folded into Q (exact).
// ---------------------------------------------------------------------------
#define AQ_PAD 68
#define AK_PAD 68
#define AV_PAD 72
#define AP_PAD 68
#define ATTN_SMEM_BYTES ((128 * AQ_PAD + 64 * AK_PAD + 64 * AV_PAD + 128 * AP_PAD) * (int)sizeof(float))

__global__ void __launch_bounds__(256, 2) attn_mma_kernel(
    const float* __restrict__ q, const float* __restrict__ kv,
    float* __restrict__ out)
{
    extern __shared__ float sm[];
    float (*Qs)[AQ_PAD] = reinterpret_cast<float(*)[AQ_PAD]>(sm);
    float (*Ks)[AK_PAD] = reinterpret_cast<float(*)[AK_PAD]>(sm + 128 * AQ_PAD);
    float (*Vs)[AV_PAD] = reinterpret_cast<float(*)[AV_PAD]>(sm + 128 * AQ_PAD + 64 * AK_PAD);
    float (*Ps)[AP_PAD] = reinterpret_cast<float(*)[AP_PAD]>(sm + 128 * AQ_PAD + 64 * AK_PAD + 64 * AV_PAD);

    const int tid  = threadIdx.x;
    const int lane = tid & 31;
    const int warp = tid >> 5;
    const int g    = lane >> 2;
    const int tg   = lane & 3;
    const int b    = blockIdx.y >> 4;
    const int h    = blockIdx.y & 15;
    const int q0   = blockIdx.x * 128;
    const int rg   = warp * 16 + g;     // this thread's first row (second: rg+8)

    // load Q tile (128 x 64), pre-scaled by 0.125 (exact in tf32)
    for (int t = tid; t < 128 * 16; t += 256) {
        int r = t >> 4, d4 = (t & 15) * 4;
        float4 v = *(const float4*)(q +
            ((((size_t)(b * NTOK + q0 + r)) * HEADS + h) << 6) + d4);
        Qs[r][d4 + 0] = v.x * 0.125f; Qs[r][d4 + 1] = v.y * 0.125f;
        Qs[r][d4 + 2] = v.z * 0.125f; Qs[r][d4 + 3] = v.w * 0.125f;
    }

    float o[8][4];
    #pragma unroll
    for (int nf = 0; nf < 8; nf++)
        #pragma unroll
        for (int r = 0; r < 4; r++) o[nf][r] = 0.f;
    float m0 = -INFINITY, m1 = -INFINITY, l0 = 0.f, l1 = 0.f;

    for (int jt = 0; jt < NTOK / 64; jt++) {
        int j0 = jt * 64;
        __syncthreads();   // WAR: previous iter's PV reads of Vs done
        for (int t = tid; t < 64 * 16; t += 256) {
            int r = t >> 4, d4 = (t & 15) * 4;
            size_t base = (size_t)(b * NTOK + j0 + r) * (2 * DMODEL) + h * HDIM + d4;
            float4 kvec = *(const float4*)(kv + base);
            float4 vvec = *(const float4*)(kv + base + DMODEL);
            Ks[r][d4 + 0] = kvec.x; Ks[r][d4 + 1] = kvec.y;
            Ks[r][d4 + 2] = kvec.z; Ks[r][d4 + 3] = kvec.w;
            Vs[r][d4 + 0] = vvec.x; Vs[r][d4 + 1] = vvec.y;
            Vs[r][d4 + 2] = vvec.z; Vs[r][d4 + 3] = vvec.w;
        }
        __syncthreads();

        // S = (Q*scale) @ K^T   (warp rows warp*16..+15, all 64 cols)
        float s[8][4];
        #pragma unroll
        for (int nf = 0; nf < 8; nf++)
            #pragma unroll
            for (int r = 0; r < 4; r++) s[nf][r] = 0.f;
        #pragma unroll
        for (int kb = 0; kb < 64; kb += 8) {
            uint32_t a0 = __float_as_uint(Qs[rg    ][kb + tg    ]);
            uint32_t a1 = __float_as_uint(Qs[rg + 8][kb + tg    ]);
            uint32_t a2 = __float_as_uint(Qs[rg    ][kb + tg + 4]);
            uint32_t a3 = __float_as_uint(Qs[rg + 8][kb + tg + 4]);
            #pragma unroll
            for (int nf = 0; nf < 8; nf++) {
                uint32_t b0 = __float_as_uint(Ks[nf * 8 + g][kb + tg    ]);
                uint32_t b1 = __float_as_uint(Ks[nf * 8 + g][kb + tg + 4]);
                mma_tf32(s[nf][0], s[nf][1], s[nf][2], s[nf][3],
                         a0, a1, a2, a3, b0, b1);
            }
        }

        // online softmax (rows rg and rg+8, owned by the 4 tg-lanes of group g)
        float mx0 = -INFINITY, mx1 = -INFINITY;
        #pragma unroll
        for (int nf = 0; nf < 8; nf++) {
            mx0 = fmaxf(mx0, fmaxf(s[nf][0], s[nf][1]));
            mx1 = fmaxf(mx1, fmaxf(s[nf][2], s[nf][3]));
        }
        mx0 = fmaxf(mx0, __shfl_xor_sync(0xffffffffu, mx0, 1));
        mx0 = fmaxf(mx0, __shfl_xor_sync(0xffffffffu, mx0, 2));
        mx1 = fmaxf(mx1, __shfl_xor_sync(0xffffffffu, mx1, 1));
        mx1 = fmaxf(mx1, __shfl_xor_sync(0xffffffffu, mx1, 2));
        float mN0 = fmaxf(m0, mx0), mN1 = fmaxf(m1, mx1);
        float c0 = __expf(m0 - mN0), c1 = __expf(m1 - mN1);
        float sum0 = 0.f, sum1 = 0.f;
        #pragma unroll
        for (int nf = 0; nf < 8; nf++) {
            s[nf][0] = __expf(s[nf][0] - mN0); sum0 += s[nf][0];
            s[nf][1] = __expf(s[nf][1] - mN0); sum0 += s[nf][1];
            s[nf][2] = __expf(s[nf][2] - mN1); sum1 += s[nf][2];
            s[nf][3] = __expf(s[nf][3] - mN1); sum1 += s[nf][3];
        }
        sum0 += __shfl_xor_sync(0xffffffffu, sum0, 1);
        sum0 += __shfl_xor_sync(0xffffffffu, sum0, 2);
        sum1 += __shfl_xor_sync(0xffffffffu, sum1, 1);
        sum1 += __shfl_xor_sync(0xffffffffu, sum1, 2);
        l0 = l0 * c0 + sum0; l1 = l1 * c1 + sum1;
        m0 = mN0; m1 = mN1;
        #pragma unroll
        for (int nf = 0; nf < 8; nf++) {
            o[nf][0] *= c0; o[nf][1] *= c0;
            o[nf][2] *= c1; o[nf][3] *= c1;
        }

        // P -> smem (RNA-rounded tf32); rows rg/rg+8 written+read by this warp only
        #pragma unroll
        for (int nf = 0; nf < 8; nf++) {
            int col = nf * 8 + 2 * tg;
            Ps[rg    ][col] = to_tf32(s[nf][0]); Ps[rg    ][col + 1] = to_tf32(s[nf][1]);
            Ps[rg + 8][col] = to_tf32(s[nf][2]); Ps[rg + 8][col + 1] = to_tf32(s[nf][3]);
        }
        __syncwarp();

        // O += P @ V
        #pragma unroll
        for (int kb = 0; kb < 64; kb += 8) {
            uint32_t a0 = __float_as_uint(Ps[rg    ][kb + tg    ]);
            uint32_t a1 = __float_as_uint(Ps[rg + 8][kb + tg    ]);
            uint32_t a2 = __float_as_uint(Ps[rg    ][kb + tg + 4]);
            uint32_t a3 = __float_as_uint(Ps[rg + 8][kb + tg + 4]);
            #pragma unroll
            for (int nf = 0; nf < 8; nf++) {
                uint32_t b0 = __float_as_uint(Vs[kb + tg    ][nf * 8 + g]);
                uint32_t b1 = __float_as_uint(Vs[kb + tg + 4][nf * 8 + g]);
                mma_tf32(o[nf][0], o[nf][1], o[nf][2], o[nf][3],
                         a0, a1, a2, a3, b0, b1);
            }
        }
    }

    // normalize + write (tf32-rounded: feeds Wo GEMM)
    float inv0 = 1.0f / l0, inv1 = 1.0f / l1;
    size_t row0 = ((((size_t)(b * NTOK + q0 + rg)) * HEADS + h) << 6);
    size_t row1 = ((((size_t)(b * NTOK + q0 + rg + 8)) * HEADS + h) << 6);
    #pragma unroll
    for (int nf = 0; nf < 8; nf++) {
        int col = nf * 8 + 2 * tg;
        float2 v0 = make_float2(to_tf32(o[nf][0] * inv0), to_tf32(o[nf][1] * inv0));
        float2 v1 = make_float2(to_tf32(o[nf][2] * inv1), to_tf32(o[nf][3] * inv1));
        *(float2*)(out + row0 + col) = v0;
        *(float2*)(out + row1 + col) = v1;
    }
}

// ---------------------------------------------------------------------------
// Launch
// ---------------------------------------------------------------------------
extern "C" void kernel_launch(void* const* d_in, const int* in_sizes, int n_in,
                              void* d_out, int out_size)
{
    const float* x    = (const float*)d_in[0];
    const float* c    = (const float*)d_in[1];
    const float* Wq   = (const float*)d_in[2];
    const float* bq   = (const float*)d_in[3];
    const float* Wkv  = (const float*)d_in[4];
    const float* bkv  = (const float*)d_in[5];
    const float* Wo   = (const float*)d_in[6];
    const float* bo   = (const float*)d_in[7];
    const float* W1   = (const float*)d_in[8];
    const float* b1   = (const float*)d_in[9];
    const float* W2   = (const float*)d_in[10];
    const float* b2   = (const float*)d_in[11];
    const float* Wada = (const float*)d_in[12];
    const float* bada = (const float*)d_in[13];
    float* out = (float*)d_out;

    float *mod, *h, *q, *kv, *att, *m1, *wq, *wkv, *wo, *w1, *w2;
    cudaGetSymbolAddress((void**)&mod, g_mod);
    cudaGetSymbolAddress((void**)&h,   g_h);
    cudaGetSymbolAddress((void**)&q,   g_q);
    cudaGetSymbolAddress((void**)&kv,  g_kv);
    cudaGetSymbolAddress((void**)&att, g_att);
    cudaGetSymbolAddress((void**)&m1,  g_m1);
    cudaGetSymbolAddress((void**)&wq,  g_wq);
    cudaGetSymbolAddress((void**)&wkv, g_wkv);
    cudaGetSymbolAddress((void**)&wo,  g_wo);
    cudaGetSymbolAddress((void**)&w1,  g_w1);
    cudaGetSymbolAddress((void**)&w2,  g_w2);

    cudaFuncSetAttribute(attn_mma_kernel,
                         cudaFuncAttributeMaxDynamicSharedMemorySize, ATTN_SMEM_BYTES);
    cudaFuncSetAttribute(mma_gemm_kernel<0>,
                         cudaFuncAttributeMaxDynamicSharedMemorySize, GEMM_SMEM_BYTES);
    cudaFuncSetAttribute(mma_gemm_kernel<1>,
                         cudaFuncAttributeMaxDynamicSharedMemorySize, GEMM_SMEM_BYTES);
    cudaFuncSetAttribute(mma_gemm_kernel<2>,
                         cudaFuncAttributeMaxDynamicSharedMemorySize, GEMM_SMEM_BYTES);

    // 0) weight rounding passes (tf32 RNA)
    round_tf32_kernel<<<(DMODEL * DMODEL / 4 + 255) / 256, 256>>>(
        (const float4*)Wq, (float4*)wq, DMODEL * DMODEL / 4);
    round_tf32_kernel<<<(DMODEL * 2 * DMODEL / 4 + 255) / 256, 256>>>(
        (const float4*)Wkv, (float4*)wkv, DMODEL * 2 * DMODEL / 4);
    round_tf32_kernel<<<(DMODEL * DMODEL / 4 + 255) / 256, 256>>>(
        (const float4*)Wo, (float4*)wo, DMODEL * DMODEL / 4);
    round_tf32_kernel<<<(DMODEL * MLPD / 4 + 255) / 256, 256>>>(
        (const float4*)W1, (float4*)w1, DMODEL * MLPD / 4);
    round_tf32_kernel<<<(MLPD * DMODEL / 4 + 255) / 256, 256>>>(
        (const float4*)W2, (float4*)w2, MLPD * DMODEL / 4);

    // 1) adaLN modulation
    ada_mod_kernel<<<dim3(SIXD / 256, BATCH), 256>>>(c, Wada, bada, mod);

    // 2) h = tf32(modulate(LN(x), sh_msa, sc_msa))
    ln_mod_kernel<<<ROWS, 256>>>(x, mod, 0 * DMODEL, 1 * DMODEL, h);

    // 3) q = h @ Wq + bq ; kv = h @ Wkv + bkv   (outputs tf32-rounded)
    mma_gemm_kernel<0><<<dim3(DMODEL / 128, ROWS / 128), 256, GEMM_SMEM_BYTES>>>(
        h, wq, bq, nullptr, nullptr, q, ROWS, DMODEL, DMODEL);
    mma_gemm_kernel<0><<<dim3(2 * DMODEL / 128, ROWS / 128), 256, GEMM_SMEM_BYTES>>>(
        h, wkv, bkv, nullptr, nullptr, kv, ROWS, 2 * DMODEL, DMODEL);

    // 4) attention (tensor-core flash)
    attn_mma_kernel<<<dim3(NTOK / 128, BATCH * HEADS), 256, ATTN_SMEM_BYTES>>>(q, kv, att);

    // 5) x1 = x + g_msa * (att @ Wo + bo)   -> d_out  (exact fp32 residual)
    mma_gemm_kernel<2><<<dim3(DMODEL / 128, ROWS / 128), 256, GEMM_SMEM_BYTES>>>(
        att, wo, bo, x, mod + 2 * DMODEL, out, ROWS, DMODEL, DMODEL);

    // 6) h2 = tf32(modulate(LN(x1), sh_mlp, sc_mlp))
    ln_mod_kernel<<<ROWS, 256>>>(out, mod, 3 * DMODEL, 4 * DMODEL, h);

    // 7) m1 = tf32(gelu(h2 @ W1 + b1))
    mma_gemm_kernel<1><<<dim3(MLPD / 128, ROWS / 128), 256, GEMM_SMEM_BYTES>>>(
        h, w1, b1, nullptr, nullptr, m1, ROWS, MLPD, DMODEL);

    // 8) x2 = x1 + g_mlp * (m1 @ W2 + b2)   -> d_out  (exact fp32 residual)
    mma_gemm_kernel<2><<<dim3(DMODEL / 128, ROWS / 128), 256, GEMM_SMEM_BYTES>>>(
        m1, w2, b2, out, mod + 5 * DMODEL, out, ROWS, DMODEL, MLPD);
}

// round 8
// speedup vs baseline: 3.3399x; 1.0264x over previous
#include <cuda_runtime.h>
#include <math.h>
#include <stdint.h>

// ---------------------------------------------------------------------------
// Problem constants
// ---------------------------------------------------------------------------
#define BATCH  4
#define NTOK   1024
#define DMODEL 1024
#define HEADS  16
#define HDIM   64
#define ROWS   (BATCH * NTOK)     // 4096
#define MLPD   4096
#define SIXD   (6 * DMODEL)       // 6144
#define EPS    1e-6f

// ---------------------------------------------------------------------------
// Scratch (device globals: no allocations allowed)
// ---------------------------------------------------------------------------
__device__ float g_mod[BATCH * SIXD];
__device__ float g_h  [ROWS * DMODEL];
__device__ float g_q  [ROWS * DMODEL];
__device__ float g_kv [ROWS * 2 * DMODEL];
__device__ float g_att[ROWS * DMODEL];
__device__ float g_m1 [ROWS * MLPD];
// tf32-rounded weights; Wq|Wkv fused into one [1024][3072] operand
__device__ float g_wqkv[DMODEL * 3 * DMODEL];
__device__ float g_wo  [DMODEL * DMODEL];
__device__ float g_w1  [DMODEL * MLPD];
__device__ float g_w2  [MLPD * DMODEL];

// ---------------------------------------------------------------------------
// Helpers
// ---------------------------------------------------------------------------
__device__ __forceinline__ float gelu_tanh(float y) {
    float y3 = y * y * y;
    return 0.5f * y * (1.0f + tanhf(0.7978845608028654f * (y + 0.044715f * y3)));
}

__device__ __forceinline__ float to_tf32(float x) {
    uint32_t y;
    asm("cvt.rna.tf32.f32 %0, %1;" : "=r"(y) : "f"(x));
    return __uint_as_float(y);
}

__device__ __forceinline__ void cp_async16(void* smem_dst, const void* gmem_src) {
    uint32_t s = (uint32_t)__cvta_generic_to_shared(smem_dst);
    asm volatile("cp.async.cg.shared.global [%0], [%1], 16;\n"
                 :: "r"(s), "l"(gmem_src));
}
__device__ __forceinline__ void cp_commit() {
    asm volatile("cp.async.commit_group;\n");
}
template <int N>
__device__ __forceinline__ void cp_wait() {
    asm volatile("cp.async.wait_group %0;\n" :: "n"(N));
}

__device__ __forceinline__ void mma_tf32(
    float& d0, float& d1, float& d2, float& d3,
    uint32_t a0, uint32_t a1, uint32_t a2, uint32_t a3,
    uint32_t b0, uint32_t b1)
{
    asm volatile(
        "mma.sync.aligned.m16n8k8.row.col.f32.tf32.tf32.f32 "
        "{%0,%1,%2,%3}, {%4,%5,%6,%7}, {%8,%9}, {%0,%1,%2,%3};"
        : "+f"(d0), "+f"(d1), "+f"(d2), "+f"(d3)
        : "r"(a0), "r"(a1), "r"(a2), "r"(a3), "r"(b0), "r"(b1));
}

// ---------------------------------------------------------------------------
// Kernel 0: round ALL weights to tf32 in one launch.
// blockIdx.y selects tensor. Wq -> wqkv cols [0,1024), Wkv -> cols [1024,3072).
// ---------------------------------------------------------------------------
__global__ void __launch_bounds__(256) round_weights_kernel(
    const float4* __restrict__ Wq, const float4* __restrict__ Wkv,
    const float4* __restrict__ Wo, const float4* __restrict__ W1,
    const float4* __restrict__ W2,
    float4* __restrict__ wqkv, float4* __restrict__ wo,
    float4* __restrict__ w1, float4* __restrict__ w2)
{
    const int t = blockIdx.y;
    const int i = blockIdx.x * 256 + threadIdx.x;
    const float4* src = nullptr;
    float4* dst = nullptr;
    int n4 = 0, di = i;
    switch (t) {
        case 0: n4 = DMODEL * DMODEL / 4;  src = Wq;  dst = wqkv;
                di = (i >> 8) * 768 + (i & 255); break;           // row*768 + col4
        case 1: n4 = DMODEL * 2 * DMODEL / 4; src = Wkv; dst = wqkv;
                di = (i >> 9) * 768 + 256 + (i & 511); break;     // row*768 + 256 + col4
        case 2: n4 = DMODEL * DMODEL / 4;  src = Wo;  dst = wo;  break;
        case 3: n4 = DMODEL * MLPD / 4;    src = W1;  dst = w1;  break;
        case 4: n4 = MLPD * DMODEL / 4;    src = W2;  dst = w2;  break;
    }
    if (i < n4) {
        float4 v = src[i];
        v.x = to_tf32(v.x); v.y = to_tf32(v.y);
        v.z = to_tf32(v.z); v.w = to_tf32(v.w);
        dst[di] = v;
    }
}

// ---------------------------------------------------------------------------
// Kernel 1: mod = silu(c) @ Wada + bada        [4, 6144]
// ---------------------------------------------------------------------------
__global__ void __launch_bounds__(256) ada_mod_kernel(
    const float* __restrict__ c, const float* __restrict__ Wada,
    const float* __restrict__ bada, float* __restrict__ mod)
{
    __shared__ float sc[DMODEL];
    int b = blockIdx.y;
    int n = blockIdx.x * 256 + threadIdx.x;
    for (int i = threadIdx.x; i < DMODEL; i += 256) {
        float v = c[b * DMODEL + i];
        sc[i] = v / (1.0f + __expf(-v));
    }
    __syncthreads();
    float acc = 0.0f;
    const float* wp = Wada + n;
    for (int k = 0; k < DMODEL; k++)
        acc = fmaf(sc[k], wp[(size_t)k * SIXD], acc);
    mod[b * SIXD + n] = acc + bada[n];
}

// ---------------------------------------------------------------------------
// Kernel 2: out = tf32(LN(x) * (1 + scale) + shift)
// ---------------------------------------------------------------------------
__global__ void __launch_bounds__(256) ln_mod_kernel(
    const float* __restrict__ x, const float* __restrict__ mod,
    int shiftOff, int scaleOff, float* __restrict__ out)
{
    __shared__ float red[8];
    int row = blockIdx.x;
    int b = row >> 10;
    const float4* xr = (const float4*)(x + (size_t)row * DMODEL);
    float4 v = xr[threadIdx.x];

    float s = v.x + v.y + v.z + v.w;
    #pragma unroll
    for (int o = 16; o; o >>= 1) s += __shfl_xor_sync(0xffffffffu, s, o);
    if ((threadIdx.x & 31) == 0) red[threadIdx.x >> 5] = s;
    __syncthreads();
    float tot = 0.f;
    #pragma unroll
    for (int w = 0; w < 8; w++) tot += red[w];
    float mean = tot * (1.0f / DMODEL);
    __syncthreads();

    float dx = v.x - mean, dy = v.y - mean, dz = v.z - mean, dw = v.w - mean;
    float q = dx * dx + dy * dy + dz * dz + dw * dw;
    #pragma unroll
    for (int o = 16; o; o >>= 1) q += __shfl_xor_sync(0xffffffffu, q, o);
    if ((threadIdx.x & 31) == 0) red[threadIdx.x >> 5] = q;
    __syncthreads();
    float vtot = 0.f;
    #pragma unroll
    for (int w = 0; w < 8; w++) vtot += red[w];
    float rstd = rsqrtf(vtot * (1.0f / DMODEL) + EPS);

    int c0 = threadIdx.x * 4;
    const float* base = mod + (size_t)b * SIXD;
    float4 shv = *(const float4*)(base + shiftOff + c0);
    float4 scv = *(const float4*)(base + scaleOff + c0);
    float4 r;
    r.x = to_tf32(dx * rstd * (1.0f + scv.x) + shv.x);
    r.y = to_tf32(dy * rstd * (1.0f + scv.y) + shv.y);
    r.z = to_tf32(dz * rstd * (1.0f + scv.z) + shv.z);
    r.w = to_tf32(dw * rstd * (1.0f + scv.w) + shv.w);
    ((float4*)(out + (size_t)row * DMODEL))[threadIdx.x] = r;
}

// ---------------------------------------------------------------------------
// Kernel 3: TF32 tensor-core GEMM, cp.async 3-stage pipeline, ONE sync/tile.
//   EPI 1: C = tf32(gelu(acc + bias[n]))
//   EPI 2: C = res + gate * (acc + bias[n])        (exact fp32 residual)
//   EPI 3: qkv split: cols [0,1024) -> C (q, ld 1024, +bias),
//                     cols [1024,3072) -> C2 (kv, ld 2048, +bias2); tf32 out
// ---------------------------------------------------------------------------
#define GSTAGES 3
#define APAD 36
#define BPAD 136
#define GEMM_SMEM_BYTES (GSTAGES * (128 * APAD + 32 * BPAD) * (int)sizeof(float))

template <int EPI>
__global__ void __launch_bounds__(256, 2) mma_gemm_kernel(
    const float* __restrict__ A, const float* __restrict__ B,
    const float* __restrict__ bias, const float* __restrict__ bias2,
    const float* __restrict__ res, const float* __restrict__ gate,
    float* __restrict__ C, float* __restrict__ C2,
    int M, int N, int K)
{
    extern __shared__ char smemRaw[];
    float (*As)[128][APAD] = reinterpret_cast<float(*)[128][APAD]>(smemRaw);
    float (*Bs)[32][BPAD]  = reinterpret_cast<float(*)[32][BPAD]>(
        smemRaw + GSTAGES * 128 * APAD * sizeof(float));

    const int tid  = threadIdx.x;
    const int lane = tid & 31;
    const int warp = tid >> 5;
    const int wm   = warp & 1;
    const int wn   = warp >> 1;
    const int bm   = blockIdx.y * 128;
    const int bn   = blockIdx.x * 128;

    const int g  = lane >> 2;
    const int tg = lane & 3;

    const int aRow0 = tid >> 3;
    const int aK4   = (tid & 7) * 4;
    const int bK0   = tid >> 5;
    const int bN4   = (tid & 31) * 4;

    float acc[4][4][4];
    #pragma unroll
    for (int i = 0; i < 4; i++)
        #pragma unroll
        for (int j = 0; j < 4; j++)
            #pragma unroll
            for (int r = 0; r < 4; r++) acc[i][j][r] = 0.f;

    const int kTiles = K >> 5;

    auto load_tile = [&](int st, int k0) {
        #pragma unroll
        for (int i = 0; i < 4; i++) {
            int r = i * 32 + aRow0;
            cp_async16(&As[st][r][aK4], A + (size_t)(bm + r) * K + k0 + aK4);
        }
        #pragma unroll
        for (int i = 0; i < 4; i++) {
            int kk = i * 8 + bK0;
            cp_async16(&Bs[st][kk][bN4], B + (size_t)(k0 + kk) * N + bn + bN4);
        }
    };

    #pragma unroll
    for (int s = 0; s < GSTAGES - 1; s++) {
        load_tile(s, s * 32);
        cp_commit();
    }

    for (int it = 0; it < kTiles; it++) {
        cp_wait<GSTAGES - 2>();
        __syncthreads();   // stage it%3 data ready AND all warps done with it (prev iter)

        int nxt = it + GSTAGES - 1;
        if (nxt < kTiles)
            load_tile(nxt % GSTAGES, nxt * 32);
        cp_commit();

        const int st = it % GSTAGES;
        #pragma unroll
        for (int ks = 0; ks < 4; ks++) {
            const int kb = ks * 8;
            uint32_t a[4][4], b[4][2];
            #pragma unroll
            for (int mf = 0; mf < 4; mf++) {
                int r = wm * 64 + mf * 16 + g;
                a[mf][0] = __float_as_uint(As[st][r    ][kb + tg    ]);
                a[mf][1] = __float_as_uint(As[st][r + 8][kb + tg    ]);
                a[mf][2] = __float_as_uint(As[st][r    ][kb + tg + 4]);
                a[mf][3] = __float_as_uint(As[st][r + 8][kb + tg + 4]);
            }
            #pragma unroll
            for (int nf = 0; nf < 4; nf++) {
                int n = wn * 32 + nf * 8 + g;
                b[nf][0] = __float_as_uint(Bs[st][kb + tg    ][n]);
                b[nf][1] = __float_as_uint(Bs[st][kb + tg + 4][n]);
            }
            #pragma unroll
            for (int mf = 0; mf < 4; mf++)
                #pragma unroll
                for (int nf = 0; nf < 4; nf++)
                    mma_tf32(acc[mf][nf][0], acc[mf][nf][1],
                             acc[mf][nf][2], acc[mf][nf][3],
                             a[mf][0], a[mf][1], a[mf][2], a[mf][3],
                             b[nf][0], b[nf][1]);
        }
        // no trailing sync: next iteration's top sync protects stage reuse
    }

    #pragma unroll
    for (int mf = 0; mf < 4; mf++) {
        #pragma unroll
        for (int half = 0; half < 2; half++) {
            int row = bm + wm * 64 + mf * 16 + g + half * 8;
            size_t gbase = (size_t)(row >> 10) * SIXD;
            #pragma unroll
            for (int nf = 0; nf < 4; nf++) {
                int col = bn + wn * 32 + nf * 8 + 2 * tg;
                float y0 = acc[mf][nf][half * 2 + 0];
                float y1 = acc[mf][nf][half * 2 + 1];
                if (EPI == 3) {
                    // block never straddles col 1024 (bn multiple of 128)
                    if (col < DMODEL) {
                        size_t rb = (size_t)row * DMODEL;
                        C[rb + col]     = to_tf32(y0 + bias[col]);
                        C[rb + col + 1] = to_tf32(y1 + bias[col + 1]);
                    } else {
                        int c2 = col - DMODEL;
                        size_t rb = (size_t)row * (2 * DMODEL);
                        C2[rb + c2]     = to_tf32(y0 + bias2[c2]);
                        C2[rb + c2 + 1] = to_tf32(y1 + bias2[c2 + 1]);
                    }
                } else {
                    size_t rbase = (size_t)row * N;
                    y0 += bias[col]; y1 += bias[col + 1];
                    if (EPI == 1) { y0 = to_tf32(gelu_tanh(y0)); y1 = to_tf32(gelu_tanh(y1)); }
                    if (EPI == 2) {
                        y0 = res[rbase + col]     + gate[gbase + col]     * y0;
                        y1 = res[rbase + col + 1] + gate[gbase + col + 1] * y1;
                    }
                    C[rbase + col]     = y0;
                    C[rbase + col + 1] = y1;
                }
            }
        }
    }
}

// ---------------------------------------------------------------------------
// Kernel 4: flash attention on tf32 tensor cores
// 8 warps x m16 = 128 q rows per block, Bc=64, d=64.
// ---------------------------------------------------------------------------
#define AQ_PAD 68
#define AK_PAD 68
#define AV_PAD 72
#define AP_PAD 68
#define ATTN_SMEM_BYTES ((128 * AQ_PAD + 64 * AK_PAD + 64 * AV_PAD + 128 * AP_PAD) * (int)sizeof(float))

__global__ void __launch_bounds__(256, 2) attn_mma_kernel(
    const float* __restrict__ q, const float* __restrict__ kv,
    float* __restrict__ out)
{
    extern __shared__ float sm[];
    float (*Qs)[AQ_PAD] = reinterpret_cast<float(*)[AQ_PAD]>(sm);
    float (*Ks)[AK_PAD] = reinterpret_cast<float(*)[AK_PAD]>(sm + 128 * AQ_PAD);
    float (*Vs)[AV_PAD] = reinterpret_cast<float(*)[AV_PAD]>(sm + 128 * AQ_PAD + 64 * AK_PAD);
    float (*Ps)[AP_PAD] = reinterpret_cast<float(*)[AP_PAD]>(sm + 128 * AQ_PAD + 64 * AK_PAD + 64 * AV_PAD);

    const int tid  = threadIdx.x;
    const int lane = tid & 31;
    const int warp = tid >> 5;
    const int g    = lane >> 2;
    const int tg   = lane & 3;
    const int b    = blockIdx.y >> 4;
    const int h    = blockIdx.y & 15;
    const int q0   = blockIdx.x * 128;
    const int rg   = warp * 16 + g;

    for (int t = tid; t < 128 * 16; t += 256) {
        int r = t >> 4, d4 = (t & 15) * 4;
        float4 v = *(const float4*)(q +
            ((((size_t)(b * NTOK + q0 + r)) * HEADS + h) << 6) + d4);
        Qs[r][d4 + 0] = v.x * 0.125f; Qs[r][d4 + 1] = v.y * 0.125f;
        Qs[r][d4 + 2] = v.z * 0.125f; Qs[r][d4 + 3] = v.w * 0.125f;
    }

    float o[8][4];
    #pragma unroll
    for (int nf = 0; nf < 8; nf++)
        #pragma unroll
        for (int r = 0; r < 4; r++) o[nf][r] = 0.f;
    float m0 = -INFINITY, m1 = -INFINITY, l0 = 0.f, l1 = 0.f;

    for (int jt = 0; jt < NTOK / 64; jt++) {
        int j0 = jt * 64;
        __syncthreads();
        for (int t = tid; t < 64 * 16; t += 256) {
            int r = t >> 4, d4 = (t & 15) * 4;
            size_t base = (size_t)(b * NTOK + j0 + r) * (2 * DMODEL) + h * HDIM + d4;
            float4 kvec = *(const float4*)(kv + base);
            float4 vvec = *(const float4*)(kv + base + DMODEL);
            Ks[r][d4 + 0] = kvec.x; Ks[r][d4 + 1] = kvec.y;
            Ks[r][d4 + 2] = kvec.z; Ks[r][d4 + 3] = kvec.w;
            Vs[r][d4 + 0] = vvec.x; Vs[r][d4 + 1] = vvec.y;
            Vs[r][d4 + 2] = vvec.z; Vs[r][d4 + 3] = vvec.w;
        }
        __syncthreads();

        float s[8][4];
        #pragma unroll
        for (int nf = 0; nf < 8; nf++)
            #pragma unroll
            for (int r = 0; r < 4; r++) s[nf][r] = 0.f;
        #pragma unroll
        for (int kb = 0; kb < 64; kb += 8) {
            uint32_t a0 = __float_as_uint(Qs[rg    ][kb + tg    ]);
            uint32_t a1 = __float_as_uint(Qs[rg + 8][kb + tg    ]);
            uint32_t a2 = __float_as_uint(Qs[rg    ][kb + tg + 4]);
            uint32_t a3 = __float_as_uint(Qs[rg + 8][kb + tg + 4]);
            #pragma unroll
            for (int nf = 0; nf < 8; nf++) {
                uint32_t b0 = __float_as_uint(Ks[nf * 8 + g][kb + tg    ]);
                uint32_t b1 = __float_as_uint(Ks[nf * 8 + g][kb + tg + 4]);
                mma_tf32(s[nf][0], s[nf][1], s[nf][2], s[nf][3],
                         a0, a1, a2, a3, b0, b1);
            }
        }

        float mx0 = -INFINITY, mx1 = -INFINITY;
        #pragma unroll
        for (int nf = 0; nf < 8; nf++) {
            mx0 = fmaxf(mx0, fmaxf(s[nf][0], s[nf][1]));
            mx1 = fmaxf(mx1, fmaxf(s[nf][2], s[nf][3]));
        }
        mx0 = fmaxf(mx0, __shfl_xor_sync(0xffffffffu, mx0, 1));
        mx0 = fmaxf(mx0, __shfl_xor_sync(0xffffffffu, mx0, 2));
        mx1 = fmaxf(mx1, __shfl_xor_sync(0xffffffffu, mx1, 1));
        mx1 = fmaxf(mx1, __shfl_xor_sync(0xffffffffu, mx1, 2));
        float mN0 = fmaxf(m0, mx0), mN1 = fmaxf(m1, mx1);
        float c0 = __expf(m0 - mN0), c1 = __expf(m1 - mN1);
        float sum0 = 0.f, sum1 = 0.f;
        #pragma unroll
        for (int nf = 0; nf < 8; nf++) {
            s[nf][0] = __expf(s[nf][0] - mN0); sum0 += s[nf][0];
            s[nf][1] = __expf(s[nf][1] - mN0); sum0 += s[nf][1];
            s[nf][2] = __expf(s[nf][2] - mN1); sum1 += s[nf][2];
            s[nf][3] = __expf(s[nf][3] - mN1); sum1 += s[nf][3];
        }
        sum0 += __shfl_xor_sync(0xffffffffu, sum0, 1);
        sum0 += __shfl_xor_sync(0xffffffffu, sum0, 2);
        sum1 += __shfl_xor_sync(0xffffffffu, sum1, 1);
        sum1 += __shfl_xor_sync(0xffffffffu, sum1, 2);
        l0 = l0 * c0 + sum0; l1 = l1 * c1 + sum1;
        m0 = mN0; m1 = mN1;
        #pragma unroll
        for (int nf = 0; nf < 8; nf++) {
            o[nf][0] *= c0; o[nf][1] *= c0;
            o[nf][2] *= c1; o[nf][3] *= c1;
        }

        #pragma unroll
        for (int nf = 0; nf < 8; nf++) {
            int col = nf * 8 + 2 * tg;
            Ps[rg    ][col] = to_tf32(s[nf][0]); Ps[rg    ][col + 1] = to_tf32(s[nf][1]);
            Ps[rg + 8][col] = to_tf32(s[nf][2]); Ps[rg + 8][col + 1] = to_tf32(s[nf][3]);
        }
        __syncwarp();

        #pragma unroll
        for (int kb = 0; kb < 64; kb += 8) {
            uint32_t a0 = __float_as_uint(Ps[rg    ][kb + tg    ]);
            uint32_t a1 = __float_as_uint(Ps[rg + 8][kb + tg    ]);
            uint32_t a2 = __float_as_uint(Ps[rg    ][kb + tg + 4]);
            uint32_t a3 = __float_as_uint(Ps[rg + 8][kb + tg + 4]);
            #pragma unroll
            for (int nf = 0; nf < 8; nf++) {
                uint32_t b0 = __float_as_uint(Vs[kb + tg    ][nf * 8 + g]);
                uint32_t b1 = __float_as_uint(Vs[kb + tg + 4][nf * 8 + g]);
                mma_tf32(o[nf][0], o[nf][1], o[nf][2], o[nf][3],
                         a0, a1, a2, a3, b0, b1);
            }
        }
    }

    float inv0 = 1.0f / l0, inv1 = 1.0f / l1;
    size_t row0 = ((((size_t)(b * NTOK + q0 + rg)) * HEADS + h) << 6);
    size_t row1 = ((((size_t)(b * NTOK + q0 + rg + 8)) * HEADS + h) << 6);
    #pragma unroll
    for (int nf = 0; nf < 8; nf++) {
        int col = nf * 8 + 2 * tg;
        float2 v0 = make_float2(to_tf32(o[nf][0] * inv0), to_tf32(o[nf][1] * inv0));
        float2 v1 = make_float2(to_tf32(o[nf][2] * inv1), to_tf32(o[nf][3] * inv1));
        *(float2*)(out + row0 + col) = v0;
        *(float2*)(out + row1 + col) = v1;
    }
}

// ---------------------------------------------------------------------------
// Launch
// ---------------------------------------------------------------------------
extern "C" void kernel_launch(void* const* d_in, const int* in_sizes, int n_in,
                              void* d_out, int out_size)
{
    const float* x    = (const float*)d_in[0];
    const float* c    = (const float*)d_in[1];
    const float* Wq   = (const float*)d_in[2];
    const float* bq   = (const float*)d_in[3];
    const float* Wkv  = (const float*)d_in[4];
    const float* bkv  = (const float*)d_in[5];
    const float* Wo   = (const float*)d_in[6];
    const float* bo   = (const float*)d_in[7];
    const float* W1   = (const float*)d_in[8];
    const float* b1   = (const float*)d_in[9];
    const float* W2   = (const float*)d_in[10];
    const float* b2   = (const float*)d_in[11];
    const float* Wada = (const float*)d_in[12];
    const float* bada = (const float*)d_in[13];
    float* out = (float*)d_out;

    float *mod, *h, *q, *kv, *att, *m1, *wqkv, *wo, *w1, *w2;
    cudaGetSymbolAddress((void**)&mod,  g_mod);
    cudaGetSymbolAddress((void**)&h,    g_h);
    cudaGetSymbolAddress((void**)&q,    g_q);
    cudaGetSymbolAddress((void**)&kv,   g_kv);
    cudaGetSymbolAddress((void**)&att,  g_att);
    cudaGetSymbolAddress((void**)&m1,   g_m1);
    cudaGetSymbolAddress((void**)&wqkv, g_wqkv);
    cudaGetSymbolAddress((void**)&wo,   g_wo);
    cudaGetSymbolAddress((void**)&w1,   g_w1);
    cudaGetSymbolAddress((void**)&w2,   g_w2);

    cudaFuncSetAttribute(attn_mma_kernel,
                         cudaFuncAttributeMaxDynamicSharedMemorySize, ATTN_SMEM_BYTES);
    cudaFuncSetAttribute(mma_gemm_kernel<1>,
                         cudaFuncAttributeMaxDynamicSharedMemorySize, GEMM_SMEM_BYTES);
    cudaFuncSetAttribute(mma_gemm_kernel<2>,
                         cudaFuncAttributeMaxDynamicSharedMemorySize, GEMM_SMEM_BYTES);
    cudaFuncSetAttribute(mma_gemm_kernel<3>,
                         cudaFuncAttributeMaxDynamicSharedMemorySize, GEMM_SMEM_BYTES);

    // 0) round all weights (one launch; Wq|Wkv fused into wqkv)
    round_weights_kernel<<<dim3(DMODEL * MLPD / 4 / 256, 5), 256>>>(
        (const float4*)Wq, (const float4*)Wkv, (const float4*)Wo,
        (const float4*)W1, (const float4*)W2,
        (float4*)wqkv, (float4*)wo, (float4*)w1, (float4*)w2);

    // 1) adaLN modulation
    ada_mod_kernel<<<dim3(SIXD / 256, BATCH), 256>>>(c, Wada, bada, mod);

    // 2) h = tf32(modulate(LN(x), sh_msa, sc_msa))
    ln_mod_kernel<<<ROWS, 256>>>(x, mod, 0 * DMODEL, 1 * DMODEL, h);

    // 3) fused QKV GEMM: [q | kv] = h @ [Wq | Wkv] + [bq | bkv]
    mma_gemm_kernel<3><<<dim3(3 * DMODEL / 128, ROWS / 128), 256, GEMM_SMEM_BYTES>>>(
        h, wqkv, bq, bkv, nullptr, nullptr, q, kv, ROWS, 3 * DMODEL, DMODEL);

    // 4) attention (tensor-core flash)
    attn_mma_kernel<<<dim3(NTOK / 128, BATCH * HEADS), 256, ATTN_SMEM_BYTES>>>(q, kv, att);

    // 5) x1 = x + g_msa * (att @ Wo + bo)   -> d_out
    mma_gemm_kernel<2><<<dim3(DMODEL / 128, ROWS / 128), 256, GEMM_SMEM_BYTES>>>(
        att, wo, bo, nullptr, x, mod + 2 * DMODEL, out, nullptr, ROWS, DMODEL, DMODEL);

    // 6) h2 = tf32(modulate(LN(x1), sh_mlp, sc_mlp))
    ln_mod_kernel<<<ROWS, 256>>>(out, mod, 3 * DMODEL, 4 * DMODEL, h);

    // 7) m1 = tf32(gelu(h2 @ W1 + b1))
    mma_gemm_kernel<1><<<dim3(MLPD / 128, ROWS / 128), 256, GEMM_SMEM_BYTES>>>(
        h, w1, b1, nullptr, nullptr, nullptr, m1, nullptr, ROWS, MLPD, DMODEL);

    // 8) x2 = x1 + g_mlp * (m1 @ W2 + b2)   -> d_out
    mma_gemm_kernel<2><<<dim3(DMODEL / 128, ROWS / 128), 256, GEMM_SMEM_BYTES>>>(
        m1, w2, b2, nullptr, out, mod + 5 * DMODEL, out, nullptr, ROWS, DMODEL, MLPD);
}

// round 9
// speedup vs baseline: 3.3886x; 1.0146x over previous
#include <cuda_runtime.h>
#include <math.h>
#include <stdint.h>

// ---------------------------------------------------------------------------
// Problem constants
// ---------------------------------------------------------------------------
#define BATCH  4
#define NTOK   1024
#define DMODEL 1024
#define HEADS  16
#define HDIM   64
#define ROWS   (BATCH * NTOK)     // 4096
#define MLPD   4096
#define SIXD   (6 * DMODEL)       // 6144
#define EPS    1e-6f

// ---------------------------------------------------------------------------
// Scratch (device globals: no allocations allowed)
// ---------------------------------------------------------------------------
__device__ float g_mod[BATCH * SIXD];
__device__ float g_h  [ROWS * DMODEL];      // K-permuted (GEMM A operand)
__device__ float g_q  [ROWS * DMODEL];      // natural (attention input)
__device__ float g_kv [ROWS * 2 * DMODEL];  // natural (attention input)
__device__ float g_att[ROWS * DMODEL];      // K-permuted (Wo A operand)
__device__ float g_m1 [ROWS * MLPD];        // K-permuted (W2 A operand)
// tf32-rounded, row-permuted weights; Wq|Wkv fused into [1024][3072]
__device__ float g_wqkv[DMODEL * 3 * DMODEL];
__device__ float g_wo  [DMODEL * DMODEL];
__device__ float g_w1  [DMODEL * MLPD];
__device__ float g_w2  [MLPD * DMODEL];

// ---------------------------------------------------------------------------
// Helpers
// ---------------------------------------------------------------------------
// K-dim permutation within each group of 8: j -> 2j (j<4), 2j-7 (j>=4).
// Makes mma fragment pair (k=tg, k=tg+4) adjacent in storage -> LDS.64.
__device__ __forceinline__ int kperm(int k) {
    return (k & ~7) | (((k & 3) << 1) | ((k >> 2) & 1));
}

__device__ __forceinline__ float gelu_tanh(float y) {
    float y3 = y * y * y;
    return 0.5f * y * (1.0f + tanhf(0.7978845608028654f * (y + 0.044715f * y3)));
}

__device__ __forceinline__ float to_tf32(float x) {
    uint32_t y;
    asm("cvt.rna.tf32.f32 %0, %1;" : "=r"(y) : "f"(x));
    return __uint_as_float(y);
}

__device__ __forceinline__ void cp_async16(void* smem_dst, const void* gmem_src) {
    uint32_t s = (uint32_t)__cvta_generic_to_shared(smem_dst);
    asm volatile("cp.async.cg.shared.global [%0], [%1], 16;\n"
                 :: "r"(s), "l"(gmem_src));
}
__device__ __forceinline__ void cp_commit() {
    asm volatile("cp.async.commit_group;\n");
}
template <int N>
__device__ __forceinline__ void cp_wait() {
    asm volatile("cp.async.wait_group %0;\n" :: "n"(N));
}

__device__ __forceinline__ void mma_tf32(
    float& d0, float& d1, float& d2, float& d3,
    uint32_t a0, uint32_t a1, uint32_t a2, uint32_t a3,
    uint32_t b0, uint32_t b1)
{
    asm volatile(
        "mma.sync.aligned.m16n8k8.row.col.f32.tf32.tf32.f32 "
        "{%0,%1,%2,%3}, {%4,%5,%6,%7}, {%8,%9}, {%0,%1,%2,%3};"
        : "+f"(d0), "+f"(d1), "+f"(d2), "+f"(d3)
        : "r"(a0), "r"(a1), "r"(a2), "r"(a3), "r"(b0), "r"(b1));
}

// ---------------------------------------------------------------------------
// Kernel 0: round ALL weights to tf32 + permute K-dim rows, one launch.
// Row permutation keeps float4 stores intact (permute row index only).
// ---------------------------------------------------------------------------
__global__ void __launch_bounds__(256) round_weights_kernel(
    const float4* __restrict__ Wq, const float4* __restrict__ Wkv,
    const float4* __restrict__ Wo, const float4* __restrict__ W1,
    const float4* __restrict__ W2,
    float4* __restrict__ wqkv, float4* __restrict__ wo,
    float4* __restrict__ w1, float4* __restrict__ w2)
{
    const int t = blockIdx.y;
    const int i = blockIdx.x * 256 + threadIdx.x;
    const float4* src = nullptr;
    float4* dst = nullptr;
    int n4 = 0, di = 0;
    switch (t) {
        case 0: n4 = DMODEL * DMODEL / 4;     src = Wq;  dst = wqkv;
                di = kperm(i >> 8) * 768 + (i & 255); break;
        case 1: n4 = DMODEL * 2 * DMODEL / 4; src = Wkv; dst = wqkv;
                di = kperm(i >> 9) * 768 + 256 + (i & 511); break;
        case 2: n4 = DMODEL * DMODEL / 4;     src = Wo;  dst = wo;
                di = kperm(i >> 8) * 256 + (i & 255); break;
        case 3: n4 = DMODEL * MLPD / 4;       src = W1;  dst = w1;
                di = kperm(i >> 10) * 1024 + (i & 1023); break;
        case 4: n4 = MLPD * DMODEL / 4;       src = W2;  dst = w2;
                di = kperm(i >> 8) * 256 + (i & 255); break;
    }
    if (i < n4) {
        float4 v = src[i];
        v.x = to_tf32(v.x); v.y = to_tf32(v.y);
        v.z = to_tf32(v.z); v.w = to_tf32(v.w);
        dst[di] = v;
    }
}

// ---------------------------------------------------------------------------
// Kernel 1: mod = silu(c) @ Wada + bada        [4, 6144]
// ---------------------------------------------------------------------------
__global__ void __launch_bounds__(256) ada_mod_kernel(
    const float* __restrict__ c, const float* __restrict__ Wada,
    const float* __restrict__ bada, float* __restrict__ mod)
{
    __shared__ float sc[DMODEL];
    int b = blockIdx.y;
    int n = blockIdx.x * 256 + threadIdx.x;
    for (int i = threadIdx.x; i < DMODEL; i += 256) {
        float v = c[b * DMODEL + i];
        sc[i] = v / (1.0f + __expf(-v));
    }
    __syncthreads();
    float acc = 0.0f;
    const float* wp = Wada + n;
    for (int k = 0; k < DMODEL; k++)
        acc = fmaf(sc[k], wp[(size_t)k * SIXD], acc);
    mod[b * SIXD + n] = acc + bada[n];
}

// ---------------------------------------------------------------------------
// Kernel 2: out = tf32(LN(x) * (1 + scale) + shift), K-permuted store
// ---------------------------------------------------------------------------
__global__ void __launch_bounds__(256) ln_mod_kernel(
    const float* __restrict__ x, const float* __restrict__ mod,
    int shiftOff, int scaleOff, float* __restrict__ out)
{
    __shared__ float red[8];
    int row = blockIdx.x;
    int b = row >> 10;
    const float4* xr = (const float4*)(x + (size_t)row * DMODEL);
    float4 v = xr[threadIdx.x];

    float s = v.x + v.y + v.z + v.w;
    #pragma unroll
    for (int o = 16; o; o >>= 1) s += __shfl_xor_sync(0xffffffffu, s, o);
    if ((threadIdx.x & 31) == 0) red[threadIdx.x >> 5] = s;
    __syncthreads();
    float tot = 0.f;
    #pragma unroll
    for (int w = 0; w < 8; w++) tot += red[w];
    float mean = tot * (1.0f / DMODEL);
    __syncthreads();

    float dx = v.x - mean, dy = v.y - mean, dz = v.z - mean, dw = v.w - mean;
    float q = dx * dx + dy * dy + dz * dz + dw * dw;
    #pragma unroll
    for (int o = 16; o; o >>= 1) q += __shfl_xor_sync(0xffffffffu, q, o);
    if ((threadIdx.x & 31) == 0) red[threadIdx.x >> 5] = q;
    __syncthreads();
    float vtot = 0.f;
    #pragma unroll
    for (int w = 0; w < 8; w++) vtot += red[w];
    float rstd = rsqrtf(vtot * (1.0f / DMODEL) + EPS);

    int c0 = threadIdx.x * 4;
    const float* base = mod + (size_t)b * SIXD;
    float4 shv = *(const float4*)(base + shiftOff + c0);
    float4 scv = *(const float4*)(base + scaleOff + c0);
    float* orow = out + (size_t)row * DMODEL;
    // permuted scatter stays inside one 32B sector: coalescing preserved
    orow[kperm(c0 + 0)] = to_tf32(dx * rstd * (1.0f + scv.x) + shv.x);
    orow[kperm(c0 + 1)] = to_tf32(dy * rstd * (1.0f + scv.y) + shv.y);
    orow[kperm(c0 + 2)] = to_tf32(dz * rstd * (1.0f + scv.z) + shv.z);
    orow[kperm(c0 + 3)] = to_tf32(dw * rstd * (1.0f + scv.w) + shv.w);
}

// ---------------------------------------------------------------------------
// Kernel 3: TF32 tensor-core GEMM, cp.async 3-stage pipeline, ONE sync/tile.
// A and B are K-permuted (within groups of 8) -> A fragments load as LDS.64.
//   EPI 1: C = tf32(gelu(acc + bias[n])), K-permuted store (feeds W2)
//   EPI 2: C = res + gate * (acc + bias[n])   (natural; exact fp32 residual)
//   EPI 3: qkv split (natural): cols<1024 -> C (+bias), else -> C2 (+bias2)
// ---------------------------------------------------------------------------
#define GSTAGES 3
#define APAD 40     // LDS.64: half-warp covers all 32 banks once
#define BPAD 132    // rows 2tg / 2tg+1 conflict-free
#define GEMM_SMEM_BYTES (GSTAGES * (128 * APAD + 32 * BPAD) * (int)sizeof(float))

template <int EPI>
__global__ void __launch_bounds__(256, 2) mma_gemm_kernel(
    const float* __restrict__ A, const float* __restrict__ B,
    const float* __restrict__ bias, const float* __restrict__ bias2,
    const float* __restrict__ res, const float* __restrict__ gate,
    float* __restrict__ C, float* __restrict__ C2,
    int M, int N, int K)
{
    extern __shared__ char smemRaw[];
    float (*As)[128][APAD] = reinterpret_cast<float(*)[128][APAD]>(smemRaw);
    float (*Bs)[32][BPAD]  = reinterpret_cast<float(*)[32][BPAD]>(
        smemRaw + GSTAGES * 128 * APAD * sizeof(float));

    const int tid  = threadIdx.x;
    const int lane = tid & 31;
    const int warp = tid >> 5;
    const int wm   = warp & 1;
    const int wn   = warp >> 1;
    const int bm   = blockIdx.y * 128;
    const int bn   = blockIdx.x * 128;

    const int g  = lane >> 2;
    const int tg = lane & 3;

    const int aRow0 = tid >> 3;
    const int aK4   = (tid & 7) * 4;
    const int bK0   = tid >> 5;
    const int bN4   = (tid & 31) * 4;

    float acc[4][4][4];
    #pragma unroll
    for (int i = 0; i < 4; i++)
        #pragma unroll
        for (int j = 0; j < 4; j++)
            #pragma unroll
            for (int r = 0; r < 4; r++) acc[i][j][r] = 0.f;

    const int kTiles = K >> 5;

    auto load_tile = [&](int st, int k0) {
        #pragma unroll
        for (int i = 0; i < 4; i++) {
            int r = i * 32 + aRow0;
            cp_async16(&As[st][r][aK4], A + (size_t)(bm + r) * K + k0 + aK4);
        }
        #pragma unroll
        for (int i = 0; i < 4; i++) {
            int kk = i * 8 + bK0;
            cp_async16(&Bs[st][kk][bN4], B + (size_t)(k0 + kk) * N + bn + bN4);
        }
    };

    #pragma unroll
    for (int s = 0; s < GSTAGES - 1; s++) {
        load_tile(s, s * 32);
        cp_commit();
    }

    for (int it = 0; it < kTiles; it++) {
        cp_wait<GSTAGES - 2>();
        __syncthreads();

        int nxt = it + GSTAGES - 1;
        if (nxt < kTiles)
            load_tile(nxt % GSTAGES, nxt * 32);
        cp_commit();

        const int st = it % GSTAGES;
        #pragma unroll
        for (int ks = 0; ks < 4; ks++) {
            const int kb = ks * 8;
            uint32_t a[4][4], b[4][2];
            #pragma unroll
            for (int mf = 0; mf < 4; mf++) {
                int r = wm * 64 + mf * 16 + g;
                // permuted layout: (k=kb+tg, k=kb+tg+4) adjacent -> LDS.64
                float2 av0 = *(const float2*)&As[st][r    ][kb + 2 * tg];
                float2 av1 = *(const float2*)&As[st][r + 8][kb + 2 * tg];
                a[mf][0] = __float_as_uint(av0.x);
                a[mf][1] = __float_as_uint(av1.x);
                a[mf][2] = __float_as_uint(av0.y);
                a[mf][3] = __float_as_uint(av1.y);
            }
            #pragma unroll
            for (int nf = 0; nf < 4; nf++) {
                int n = wn * 32 + nf * 8 + g;
                b[nf][0] = __float_as_uint(Bs[st][kb + 2 * tg    ][n]);
                b[nf][1] = __float_as_uint(Bs[st][kb + 2 * tg + 1][n]);
            }
            #pragma unroll
            for (int mf = 0; mf < 4; mf++)
                #pragma unroll
                for (int nf = 0; nf < 4; nf++)
                    mma_tf32(acc[mf][nf][0], acc[mf][nf][1],
                             acc[mf][nf][2], acc[mf][nf][3],
                             a[mf][0], a[mf][1], a[mf][2], a[mf][3],
                             b[nf][0], b[nf][1]);
        }
    }

    #pragma unroll
    for (int mf = 0; mf < 4; mf++) {
        #pragma unroll
        for (int half = 0; half < 2; half++) {
            int row = bm + wm * 64 + mf * 16 + g + half * 8;
            size_t gbase = (size_t)(row >> 10) * SIXD;
            #pragma unroll
            for (int nf = 0; nf < 4; nf++) {
                int col = bn + wn * 32 + nf * 8 + 2 * tg;
                float y0 = acc[mf][nf][half * 2 + 0];
                float y1 = acc[mf][nf][half * 2 + 1];
                if (EPI == 3) {
                    if (col < DMODEL) {
                        size_t rb = (size_t)row * DMODEL;
                        C[rb + col]     = to_tf32(y0 + bias[col]);
                        C[rb + col + 1] = to_tf32(y1 + bias[col + 1]);
                    } else {
                        int c2 = col - DMODEL;
                        size_t rb = (size_t)row * (2 * DMODEL);
                        C2[rb + c2]     = to_tf32(y0 + bias2[c2]);
                        C2[rb + c2 + 1] = to_tf32(y1 + bias2[c2 + 1]);
                    }
                } else if (EPI == 1) {
                    size_t rbase = (size_t)row * N;
                    // K-permuted store: m1 is the next GEMM's A operand
                    C[rbase + kperm(col)]     = to_tf32(gelu_tanh(y0 + bias[col]));
                    C[rbase + kperm(col + 1)] = to_tf32(gelu_tanh(y1 + bias[col + 1]));
                } else {
                    size_t rbase = (size_t)row * N;
                    y0 = res[rbase + col]     + gate[gbase + col]     * (y0 + bias[col]);
                    y1 = res[rbase + col + 1] + gate[gbase + col + 1] * (y1 + bias[col + 1]);
                    C[rbase + col]     = y0;
                    C[rbase + col + 1] = y1;
                }
            }
        }
    }
}

// ---------------------------------------------------------------------------
// Kernel 4: flash attention on tf32 tensor cores
// 8 warps x m16 = 128 q rows per block, Bc=64, d=64.
// Output store is K-permuted (att feeds the Wo GEMM as A).
// ---------------------------------------------------------------------------
#define AQ_PAD 68
#define AK_PAD 68
#define AV_PAD 72
#define AP_PAD 68
#define ATTN_SMEM_BYTES ((128 * AQ_PAD + 64 * AK_PAD + 64 * AV_PAD + 128 * AP_PAD) * (int)sizeof(float))

__global__ void __launch_bounds__(256, 2) attn_mma_kernel(
    const float* __restrict__ q, const float* __restrict__ kv,
    float* __restrict__ out)
{
    extern __shared__ float sm[];
    float (*Qs)[AQ_PAD] = reinterpret_cast<float(*)[AQ_PAD]>(sm);
    float (*Ks)[AK_PAD] = reinterpret_cast<float(*)[AK_PAD]>(sm + 128 * AQ_PAD);
    float (*Vs)[AV_PAD] = reinterpret_cast<float(*)[AV_PAD]>(sm + 128 * AQ_PAD + 64 * AK_PAD);
    float (*Ps)[AP_PAD] = reinterpret_cast<float(*)[AP_PAD]>(sm + 128 * AQ_PAD + 64 * AK_PAD + 64 * AV_PAD);

    const int tid  = threadIdx.x;
    const int lane = tid & 31;
    const int warp = tid >> 5;
    const int g    = lane >> 2;
    const int tg   = lane & 3;
    const int b    = blockIdx.y >> 4;
    const int h    = blockIdx.y & 15;
    const int q0   = blockIdx.x * 128;
    const int rg   = warp * 16 + g;

    for (int t = tid; t < 128 * 16; t += 256) {
        int r = t >> 4, d4 = (t & 15) * 4;
        float4 v = *(const float4*)(q +
            ((((size_t)(b * NTOK + q0 + r)) * HEADS + h) << 6) + d4);
        Qs[r][d4 + 0] = v.x * 0.125f; Qs[r][d4 + 1] = v.y * 0.125f;
        Qs[r][d4 + 2] = v.z * 0.125f; Qs[r][d4 + 3] = v.w * 0.125f;
    }

    float o[8][4];
    #pragma unroll
    for (int nf = 0; nf < 8; nf++)
        #pragma unroll
        for (int r = 0; r < 4; r++) o[nf][r] = 0.f;
    float m0 = -INFINITY, m1 = -INFINITY, l0 = 0.f, l1 = 0.f;

    for (int jt = 0; jt < NTOK / 64; jt++) {
        int j0 = jt * 64;
        __syncthreads();
        for (int t = tid; t < 64 * 16; t += 256) {
            int r = t >> 4, d4 = (t & 15) * 4;
            size_t base = (size_t)(b * NTOK + j0 + r) * (2 * DMODEL) + h * HDIM + d4;
            float4 kvec = *(const float4*)(kv + base);
            float4 vvec = *(const float4*)(kv + base + DMODEL);
            Ks[r][d4 + 0] = kvec.x; Ks[r][d4 + 1] = kvec.y;
            Ks[r][d4 + 2] = kvec.z; Ks[r][d4 + 3] = kvec.w;
            Vs[r][d4 + 0] = vvec.x; Vs[r][d4 + 1] = vvec.y;
            Vs[r][d4 + 2] = vvec.z; Vs[r][d4 + 3] = vvec.w;
        }
        __syncthreads();

        float s[8][4];
        #pragma unroll
        for (int nf = 0; nf < 8; nf++)
            #pragma unroll
            for (int r = 0; r < 4; r++) s[nf][r] = 0.f;
        #pragma unroll
        for (int kb = 0; kb < 64; kb += 8) {
            uint32_t a0 = __float_as_uint(Qs[rg    ][kb + tg    ]);
            uint32_t a1 = __float_as_uint(Qs[rg + 8][kb + tg    ]);
            uint32_t a2 = __float_as_uint(Qs[rg    ][kb + tg + 4]);
            uint32_t a3 = __float_as_uint(Qs[rg + 8][kb + tg + 4]);
            #pragma unroll
            for (int nf = 0; nf < 8; nf++) {
                uint32_t b0 = __float_as_uint(Ks[nf * 8 + g][kb + tg    ]);
                uint32_t b1 = __float_as_uint(Ks[nf * 8 + g][kb + tg + 4]);
                mma_tf32(s[nf][0], s[nf][1], s[nf][2], s[nf][3],
                         a0, a1, a2, a3, b0, b1);
            }
        }

        float mx0 = -INFINITY, mx1 = -INFINITY;
        #pragma unroll
        for (int nf = 0; nf < 8; nf++) {
            mx0 = fmaxf(mx0, fmaxf(s[nf][0], s[nf][1]));
            mx1 = fmaxf(mx1, fmaxf(s[nf][2], s[nf][3]));
        }
        mx0 = fmaxf(mx0, __shfl_xor_sync(0xffffffffu, mx0, 1));
        mx0 = fmaxf(mx0, __shfl_xor_sync(0xffffffffu, mx0, 2));
        mx1 = fmaxf(mx1, __shfl_xor_sync(0xffffffffu, mx1, 1));
        mx1 = fmaxf(mx1, __shfl_xor_sync(0xffffffffu, mx1, 2));
        float mN0 = fmaxf(m0, mx0), mN1 = fmaxf(m1, mx1);
        float c0 = __expf(m0 - mN0), c1 = __expf(m1 - mN1);
        float sum0 = 0.f, sum1 = 0.f;
        #pragma unroll
        for (int nf = 0; nf < 8; nf++) {
            s[nf][0] = __expf(s[nf][0] - mN0); sum0 += s[nf][0];
            s[nf][1] = __expf(s[nf][1] - mN0); sum0 += s[nf][1];
            s[nf][2] = __expf(s[nf][2] - mN1); sum1 += s[nf][2];
            s[nf][3] = __expf(s[nf][3] - mN1); sum1 += s[nf][3];
        }
        sum0 += __shfl_xor_sync(0xffffffffu, sum0, 1);
        sum0 += __shfl_xor_sync(0xffffffffu, sum0, 2);
        sum1 += __shfl_xor_sync(0xffffffffu, sum1, 1);
        sum1 += __shfl_xor_sync(0xffffffffu, sum1, 2);
        l0 = l0 * c0 + sum0; l1 = l1 * c1 + sum1;
        m0 = mN0; m1 = mN1;
        #pragma unroll
        for (int nf = 0; nf < 8; nf++) {
            o[nf][0] *= c0; o[nf][1] *= c0;
            o[nf][2] *= c1; o[nf][3] *= c1;
        }

        #pragma unroll
        for (int nf = 0; nf < 8; nf++) {
            int col = nf * 8 + 2 * tg;
            Ps[rg    ][col] = to_tf32(s[nf][0]); Ps[rg    ][col + 1] = to_tf32(s[nf][1]);
            Ps[rg + 8][col] = to_tf32(s[nf][2]); Ps[rg + 8][col + 1] = to_tf32(s[nf][3]);
        }
        __syncwarp();

        #pragma unroll
        for (int kb = 0; kb < 64; kb += 8) {
            uint32_t a0 = __float_as_uint(Ps[rg    ][kb + tg    ]);
            uint32_t a1 = __float_as_uint(Ps[rg + 8][kb + tg    ]);
            uint32_t a2 = __float_as_uint(Ps[rg    ][kb + tg + 4]);
            uint32_t a3 = __float_as_uint(Ps[rg + 8][kb + tg + 4]);
            #pragma unroll
            for (int nf = 0; nf < 8; nf++) {
                uint32_t b0 = __float_as_uint(Vs[kb + tg    ][nf * 8 + g]);
                uint32_t b1 = __float_as_uint(Vs[kb + tg + 4][nf * 8 + g]);
                mma_tf32(o[nf][0], o[nf][1], o[nf][2], o[nf][3],
                         a0, a1, a2, a3, b0, b1);
            }
        }
    }

    // normalize + write, K-permuted (att is the Wo GEMM's A operand)
    float inv0 = 1.0f / l0, inv1 = 1.0f / l1;
    size_t row0 = ((((size_t)(b * NTOK + q0 + rg)) * HEADS + h) << 6);
    size_t row1 = ((((size_t)(b * NTOK + q0 + rg + 8)) * HEADS + h) << 6);
    #pragma unroll
    for (int nf = 0; nf < 8; nf++) {
        int col = nf * 8 + 2 * tg;
        out[row0 + kperm(col)]     = to_tf32(o[nf][0] * inv0);
        out[row0 + kperm(col + 1)] = to_tf32(o[nf][1] * inv0);
        out[row1 + kperm(col)]     = to_tf32(o[nf][2] * inv1);
        out[row1 + kperm(col + 1)] = to_tf32(o[nf][3] * inv1);
    }
}

// ---------------------------------------------------------------------------
// Launch
// ---------------------------------------------------------------------------
extern "C" void kernel_launch(void* const* d_in, const int* in_sizes, int n_in,
                              void* d_out, int out_size)
{
    const float* x    = (const float*)d_in[0];
    const float* c    = (const float*)d_in[1];
    const float* Wq   = (const float*)d_in[2];
    const float* bq   = (const float*)d_in[3];
    const float* Wkv  = (const float*)d_in[4];
    const float* bkv  = (const float*)d_in[5];
    const float* Wo   = (const float*)d_in[6];
    const float* bo   = (const float*)d_in[7];
    const float* W1   = (const float*)d_in[8];
    const float* b1   = (const float*)d_in[9];
    const float* W2   = (const float*)d_in[10];
    const float* b2   = (const float*)d_in[11];
    const float* Wada = (const float*)d_in[12];
    const float* bada = (const float*)d_in[13];
    float* out = (float*)d_out;

    float *mod, *h, *q, *kv, *att, *m1, *wqkv, *wo, *w1, *w2;
    cudaGetSymbolAddress((void**)&mod,  g_mod);
    cudaGetSymbolAddress((void**)&h,    g_h);
    cudaGetSymbolAddress((void**)&q,    g_q);
    cudaGetSymbolAddress((void**)&kv,   g_kv);
    cudaGetSymbolAddress((void**)&att,  g_att);
    cudaGetSymbolAddress((void**)&m1,   g_m1);
    cudaGetSymbolAddress((void**)&wqkv, g_wqkv);
    cudaGetSymbolAddress((void**)&wo,   g_wo);
    cudaGetSymbolAddress((void**)&w1,   g_w1);
    cudaGetSymbolAddress((void**)&w2,   g_w2);

    cudaFuncSetAttribute(attn_mma_kernel,
                         cudaFuncAttributeMaxDynamicSharedMemorySize, ATTN_SMEM_BYTES);
    cudaFuncSetAttribute(mma_gemm_kernel<1>,
                         cudaFuncAttributeMaxDynamicSharedMemorySize, GEMM_SMEM_BYTES);
    cudaFuncSetAttribute(mma_gemm_kernel<2>,
                         cudaFuncAttributeMaxDynamicSharedMemorySize, GEMM_SMEM_BYTES);
    cudaFuncSetAttribute(mma_gemm_kernel<3>,
                         cudaFuncAttributeMaxDynamicSharedMemorySize, GEMM_SMEM_BYTES);

    // 0) round + row-permute all weights (one launch)
    round_weights_kernel<<<dim3(DMODEL * MLPD / 4 / 256, 5), 256>>>(
        (const float4*)Wq, (const float4*)Wkv, (const float4*)Wo,
        (const float4*)W1, (const float4*)W2,
        (float4*)wqkv, (float4*)wo, (float4*)w1, (float4*)w2);

    // 1) adaLN modulation
    ada_mod_kernel<<<dim3(SIXD / 256, BATCH), 256>>>(c, Wada, bada, mod);

    // 2) h = tf32(modulate(LN(x), sh_msa, sc_msa)), K-permuted
    ln_mod_kernel<<<ROWS, 256>>>(x, mod, 0 * DMODEL, 1 * DMODEL, h);

    // 3) fused QKV GEMM: [q | kv] = h @ [Wq | Wkv] + [bq | bkv]  (natural out)
    mma_gemm_kernel<3><<<dim3(3 * DMODEL / 128, ROWS / 128), 256, GEMM_SMEM_BYTES>>>(
        h, wqkv, bq, bkv, nullptr, nullptr, q, kv, ROWS, 3 * DMODEL, DMODEL);

    // 4) attention (tensor-core flash; K-permuted att out)
    attn_mma_kernel<<<dim3(NTOK / 128, BATCH * HEADS), 256, ATTN_SMEM_BYTES>>>(q, kv, att);

    // 5) x1 = x + g_msa * (att @ Wo + bo)   -> d_out (natural)
    mma_gemm_kernel<2><<<dim3(DMODEL / 128, ROWS / 128), 256, GEMM_SMEM_BYTES>>>(
        att, wo, bo, nullptr, x, mod + 2 * DMODEL, out, nullptr, ROWS, DMODEL, DMODEL);

    // 6) h2 = tf32(modulate(LN(x1), sh_mlp, sc_mlp)), K-permuted
    ln_mod_kernel<<<ROWS, 256>>>(out, mod, 3 * DMODEL, 4 * DMODEL, h);

    // 7) m1 = tf32(gelu(h2 @ W1 + b1)), K-permuted store
    mma_gemm_kernel<1><<<dim3(MLPD / 128, ROWS / 128), 256, GEMM_SMEM_BYTES>>>(
        h, w1, b1, nullptr, nullptr, nullptr, m1, nullptr, ROWS, MLPD, DMODEL);

    // 8) x2 = x1 + g_mlp * (m1 @ W2 + b2)   -> d_out (natural)
    mma_gemm_kernel<2><<<dim3(DMODEL / 128, ROWS / 128), 256, GEMM_SMEM_BYTES>>>(
        m1, w2, b2, nullptr, out, mod + 5 * DMODEL, out, nullptr, ROWS, DMODEL, MLPD);
}